// round 11
// baseline (speedup 1.0000x reference)
#include <cuda_runtime.h>
#include <cuda_bf16.h>
#include <math.h>
#include <stdint.h>

#define B_  8
#define T_  12
#define N_  1024
#define C_  64
#define D_  10
#define BT_ (B_*T_)   // 96

// ======================= mma.sync / ldmatrix helpers ========================
__device__ __forceinline__ uint32_t sm_addr(const void* p) {
    return (uint32_t)__cvta_generic_to_shared(p);
}
__device__ __forceinline__ void ldsm_x4(unsigned* r, uint32_t a) {
    asm volatile("ldmatrix.sync.aligned.m8n8.x4.shared.b16 {%0,%1,%2,%3}, [%4];"
                 : "=r"(r[0]), "=r"(r[1]), "=r"(r[2]), "=r"(r[3]) : "r"(a));
}
__device__ __forceinline__ void ldsm_x4t(unsigned* r, uint32_t a) {
    asm volatile("ldmatrix.sync.aligned.m8n8.x4.trans.shared.b16 {%0,%1,%2,%3}, [%4];"
                 : "=r"(r[0]), "=r"(r[1]), "=r"(r[2]), "=r"(r[3]) : "r"(a));
}
__device__ __forceinline__ void mma16816(float* d, const unsigned* a, const unsigned* b) {
    asm volatile("mma.sync.aligned.m16n8k16.row.col.f32.bf16.bf16.f32 "
                 "{%0,%1,%2,%3}, {%4,%5,%6,%7}, {%8,%9}, {%0,%1,%2,%3};"
                 : "+f"(d[0]), "+f"(d[1]), "+f"(d[2]), "+f"(d[3])
                 : "r"(a[0]), "r"(a[1]), "r"(a[2]), "r"(a[3]),
                   "r"(b[0]), "r"(b[1]));
}
__device__ __forceinline__ void split_bf16(float v, __nv_bfloat16& h, __nv_bfloat16& l) {
    h = __float2bfloat16(v);
    l = __float2bfloat16(v - __bfloat162float(h));
}
__device__ __forceinline__ unsigned pack2(__nv_bfloat16 lo, __nv_bfloat16 hi) {
    __nv_bfloat162 v = __halves2bfloat162(lo, hi);
    return *reinterpret_cast<unsigned*>(&v);
}

// stage rows x (COLS8*8) bf16 tile gmem->smem (padded pitch, 16B vectors)
template<int COLS8>
__device__ __forceinline__ void stage(__nv_bfloat16* s, int pitch,
                                      const __nv_bfloat16* __restrict__ g,
                                      size_t gstride, int rows) {
    int tot = rows * COLS8;
    for (int i = threadIdx.x; i < tot; i += blockDim.x) {
        int r = i / COLS8, c = (i % COLS8) * 8;
        *(uint4*)(s + r*pitch + c) = *(const uint4*)(g + (size_t)r*gstride + c);
    }
}

// warp-level split-bf16 MMA over one 64-K chunk (MI m-tiles x 32 n)
template<int MI>
__device__ __forceinline__ void warp_mma(float (&acc)[MI][4][4],
        const __nv_bfloat16* Ah, const __nv_bfloat16* Al, int pa,
        const __nv_bfloat16* Bh, const __nv_bfloat16* Bl, int pb,
        int m_base, int n_base, int lane) {
    const int ar = lane & 15, ac = (lane >> 4) * 8;
#pragma unroll
    for (int ks = 0; ks < 4; ks++) {
        unsigned ah[MI][4], al[MI][4], bh[2][4], bl[2][4];
#pragma unroll
        for (int mi = 0; mi < MI; mi++) {
            int off = (m_base + mi*16 + ar)*pa + ks*16 + ac;
            ldsm_x4(ah[mi], sm_addr(Ah + off));
            ldsm_x4(al[mi], sm_addr(Al + off));
        }
#pragma unroll
        for (int njp = 0; njp < 2; njp++) {
            int off = (ks*16 + ar)*pb + n_base + njp*16 + ac;
            ldsm_x4t(bh[njp], sm_addr(Bh + off));
            ldsm_x4t(bl[njp], sm_addr(Bl + off));
        }
#pragma unroll
        for (int mi = 0; mi < MI; mi++)
#pragma unroll
            for (int j = 0; j < 4; j++) {
                const unsigned* ph = &bh[j>>1][(j&1)*2];
                const unsigned* pl = &bl[j>>1][(j&1)*2];
                mma16816(acc[mi][j], ah[mi], ph);
                mma16816(acc[mi][j], ah[mi], pl);
                mma16816(acc[mi][j], al[mi], ph);
            }
    }
}

// ======================= scratch globals ====================================
__device__ float         g_supports[N_*N_];
__device__ __nv_bfloat16 g_sup_hi[N_*N_], g_sup_lo[N_*N_];
__device__ __nv_bfloat16 g_A_hi[N_*N_],   g_A_lo[N_*N_];
__device__ __nv_bfloat16 g_x_hi[(size_t)BT_*N_*C_],  g_x_lo[(size_t)BT_*N_*C_];
__device__ __nv_bfloat16 g_xT_hi[(size_t)BT_*C_*N_], g_xT_lo[(size_t)BT_*C_*N_];
__device__ __nv_bfloat16 g_wp_hi[(size_t)1024*4096], g_wp_lo[(size_t)1024*4096];
__device__ float         g_weights[N_*C_*C_];
__device__ float         g_bias[N_*C_];
__device__ float         g_bias_part[8*N_*C_];
__device__ float         g_score[(size_t)BT_*N_*N_];   // 402 MB
__device__ float         g_lse[(size_t)B_*N_*N_];      //  32 MB
__device__ float         g_xg[(size_t)BT_*N_*C_];

// ======================= small kernels ======================================
__global__ void k_supports(const float* __restrict__ e1,
                           const float* __restrict__ e2) {
    int j = blockIdx.x * 16 + threadIdx.x;
    int i = blockIdx.y * 16 + threadIdx.y;
    float d = 0.f;
#pragma unroll
    for (int k = 0; k < D_; k++)
        d += e1[i*D_+k]*e2[j*D_+k] - e2[i*D_+k]*e1[j*D_+k];
    float v = fmaxf(tanhf(d), 0.f);
    if (i == j) v += 1.f;
    g_supports[i*N_ + j] = v;
    __nv_bfloat16 h, l; split_bf16(v, h, l);
    g_sup_hi[i*N_ + j] = h; g_sup_lo[i*N_ + j] = l;
}

__global__ void k_softmaxA(const float* __restrict__ A_sym) {
    int row = blockIdx.x, t = threadIdx.x;
    const float* r = A_sym + (size_t)row * N_;
    __shared__ float red[256];
    float vals[4]; float m = -3.4e38f;
#pragma unroll
    for (int q = 0; q < 4; q++) { vals[q] = r[t + q*256]; m = fmaxf(m, vals[q]); }
    red[t] = m; __syncthreads();
    for (int s = 128; s > 0; s >>= 1) { if (t < s) red[t] = fmaxf(red[t], red[t+s]); __syncthreads(); }
    m = red[0]; __syncthreads();
    float sum = 0.f;
#pragma unroll
    for (int q = 0; q < 4; q++) { vals[q] = expf(vals[q] - m); sum += vals[q]; }
    red[t] = sum; __syncthreads();
    for (int s = 128; s > 0; s >>= 1) { if (t < s) red[t] += red[t+s]; __syncthreads(); }
    float inv = 1.f / red[0];
#pragma unroll
    for (int q = 0; q < 4; q++) {
        float v = vals[q] * inv;
        __nv_bfloat16 h, l; split_bf16(v, h, l);
        size_t idx = (size_t)row*N_ + t + q*256;
        g_A_hi[idx] = h; g_A_lo[idx] = l;
    }
}

__global__ void k_cvt_x(const float* __restrict__ x) {
    int bt = blockIdx.y, n0 = blockIdx.x * 64;
    __shared__ float tbuf[64][65];
    int tid = threadIdx.x;
    for (int e = tid; e < 4096; e += 256) {
        int n = e >> 6, c = e & 63;
        float v = x[((size_t)bt*N_ + n0 + n)*C_ + c];
        tbuf[n][c] = v;
        __nv_bfloat16 h, l; split_bf16(v, h, l);
        size_t idx = ((size_t)bt*N_ + n0 + n)*C_ + c;
        g_x_hi[idx] = h; g_x_lo[idx] = l;
    }
    __syncthreads();
    for (int e = tid; e < 4096; e += 256) {
        int c = e >> 6, n = e & 63;
        float v = tbuf[n][c];
        __nv_bfloat16 h, l; split_bf16(v, h, l);
        size_t idx = ((size_t)bt*C_ + c)*N_ + n0 + n;
        g_xT_hi[idx] = h; g_xT_lo[idx] = l;
    }
}

__global__ void k_cvt_wp(const float* __restrict__ wp) {
    size_t i = ((size_t)blockIdx.x*256 + threadIdx.x)*4;
    float4 v = *(const float4*)(wp + i);
    __nv_bfloat16 h, l;
    split_bf16(v.x, h, l); g_wp_hi[i+0] = h; g_wp_lo[i+0] = l;
    split_bf16(v.y, h, l); g_wp_hi[i+1] = h; g_wp_lo[i+1] = l;
    split_bf16(v.z, h, l); g_wp_hi[i+2] = h; g_wp_lo[i+2] = l;
    split_bf16(v.w, h, l); g_wp_hi[i+3] = h; g_wp_lo[i+3] = l;
}

// ======================= weights GEMM =======================================
#define OW_AH 0
#define OW_AL 9216
#define OW_BH 18432
#define OW_BL 27136
#define SMW_BYTES ((27136 + 8704) * 2)

__global__ void __launch_bounds__(256) k_weights_mma() {
    extern __shared__ __nv_bfloat16 sm[];
    const int n0 = blockIdx.y * 128, io0 = blockIdx.x * 128;
    const int tid = threadIdx.x, wid = tid >> 5, lane = tid & 31;
    const int m_base = (wid >> 2) * 64, n_base = (wid & 3) * 32;
    float acc[4][4][4] = {};
    for (int ch = 0; ch < 16; ch++) {
        int ko = ch * 64;
        stage<8> (sm+OW_AH,  72, g_sup_hi + (size_t)n0*N_ + ko, N_, 128);
        stage<8> (sm+OW_AL,  72, g_sup_lo + (size_t)n0*N_ + ko, N_, 128);
        stage<16>(sm+OW_BH, 136, g_wp_hi + (size_t)ko*4096 + io0, 4096, 64);
        stage<16>(sm+OW_BL, 136, g_wp_lo + (size_t)ko*4096 + io0, 4096, 64);
        __syncthreads();
        warp_mma<4>(acc, sm+OW_AH, sm+OW_AL, 72, sm+OW_BH, sm+OW_BL, 136,
                    m_base, n_base, lane);
        __syncthreads();
    }
#pragma unroll
    for (int mi = 0; mi < 4; mi++)
#pragma unroll
        for (int j = 0; j < 4; j++) {
            int r = n0 + m_base + mi*16 + (lane >> 2);
            int c = io0 + n_base + j*8 + (lane & 3)*2;
            g_weights[(size_t)r*4096 + c]       = acc[mi][j][0];
            g_weights[(size_t)r*4096 + c + 1]   = acc[mi][j][1];
            g_weights[(size_t)(r+8)*4096 + c]   = acc[mi][j][2];
            g_weights[(size_t)(r+8)*4096 + c+1] = acc[mi][j][3];
        }
}

// ======================= score GEMM (writes fp32 score) =====================
__global__ void __launch_bounds__(256) k_score_mma() {
    extern __shared__ __nv_bfloat16 sm[];
    const int bt = blockIdx.z, n0 = blockIdx.y * 128, m0 = blockIdx.x * 128;
    const int tid = threadIdx.x, wid = tid >> 5, lane = tid & 31;
    const int m_base = (wid >> 2) * 64, n_base = (wid & 3) * 32;
    float acc[4][4][4] = {};
    stage<8> (sm+OW_AH,  72, g_x_hi + ((size_t)bt*N_ + n0)*C_, C_, 128);
    stage<8> (sm+OW_AL,  72, g_x_lo + ((size_t)bt*N_ + n0)*C_, C_, 128);
    stage<16>(sm+OW_BH, 136, g_xT_hi + (size_t)bt*C_*N_ + m0, N_, 64);
    stage<16>(sm+OW_BL, 136, g_xT_lo + (size_t)bt*C_*N_ + m0, N_, 64);
    __syncthreads();
    warp_mma<4>(acc, sm+OW_AH, sm+OW_AL, 72, sm+OW_BH, sm+OW_BL, 136,
                m_base, n_base, lane);
    float* S = g_score + (size_t)bt*N_*N_;
#pragma unroll
    for (int mi = 0; mi < 4; mi++)
#pragma unroll
        for (int j = 0; j < 4; j++) {
            int r = n0 + m_base + mi*16 + (lane >> 2);
            int c = m0 + n_base + j*8 + (lane & 3)*2;
            S[(size_t)r*N_ + c]       = acc[mi][j][0];
            S[(size_t)r*N_ + c + 1]   = acc[mi][j][1];
            S[(size_t)(r+8)*N_ + c]   = acc[mi][j][2];
            S[(size_t)(r+8)*N_ + c+1] = acc[mi][j][3];
        }
}

// ======================= LSE over T: stable log-sum-exp ======================
__global__ void k_lse() {
    size_t idx = (size_t)blockIdx.x * blockDim.x + threadIdx.x;  // B*N*N
    int b = (int)(idx >> 20);
    size_t r = idx & ((size_t)N_*N_ - 1);
    size_t base = (size_t)b * T_ * N_ * N_ + r;
    float v[T_]; float m = -3.4e38f;
#pragma unroll
    for (int t = 0; t < T_; t++) {
        v[t] = g_score[base + (size_t)t * N_ * N_];
        m = fmaxf(m, v[t]);
    }
    float sum = 0.f;
#pragma unroll
    for (int t = 0; t < T_; t++) sum += __expf(v[t] - m);
    g_lse[idx] = m + __logf(sum);
}

// ======================= sa: out += beta*relu(P @ X), P from gmem score =====
// block (128 n-rows, bt); 8 warps x 16 rows. Per 64-m chunk: load score
// C-frags from gmem, P = exp(s - LSE), split->A-frags, PV MMA.
#define SG_PVH 0
#define SG_PVL 4608
#define SMSG_BYTES (9216 * 2)   // 18 KB

__global__ void __launch_bounds__(256) k_sa_gmem(const float* __restrict__ beta,
                                                 float* __restrict__ out) {
    extern __shared__ __nv_bfloat16 sm[];
    const int bt = blockIdx.y, b = bt / T_;
    const int n0 = blockIdx.x * 128;
    const int tid = threadIdx.x, wid = tid >> 5, lane = tid & 31;
    const int ar = lane & 15, ac = (lane >> 4) * 8;
    const int rq = lane >> 2, cp = (lane & 3) * 2;
    const int gr = n0 + wid*16 + rq;

    const float* Sc = g_score + (size_t)bt*N_*N_;
    const float* Lb = g_lse   + (size_t)b*N_*N_;
    float oacc[8][4] = {};

    for (int mc = 0; mc < 16; mc++) {
        const int m0 = mc * 64;
        __syncthreads();
        stage<8>(sm+SG_PVH, 72, g_x_hi + ((size_t)bt*N_ + m0)*C_, C_, 64);
        stage<8>(sm+SG_PVL, 72, g_x_lo + ((size_t)bt*N_ + m0)*C_, C_, 64);
        __syncthreads();
#pragma unroll
        for (int kg = 0; kg < 4; kg++) {
            unsigned ph[4], pl[4];
#pragma unroll
            for (int jj = 0; jj < 2; jj++) {
                int gc = m0 + (2*kg + jj)*8 + cp;
                float2 s0 = *(const float2*)(Sc + (size_t)gr*N_ + gc);
                float2 s8 = *(const float2*)(Sc + (size_t)(gr+8)*N_ + gc);
                float2 l0 = *(const float2*)(Lb + (size_t)gr*N_ + gc);
                float2 l8 = *(const float2*)(Lb + (size_t)(gr+8)*N_ + gc);
                float p0 = __expf(s0.x - l0.x);
                float p1 = __expf(s0.y - l0.y);
                float p2 = __expf(s8.x - l8.x);
                float p3 = __expf(s8.y - l8.y);
                __nv_bfloat16 h0, lo0, h1, lo1, h2, lo2, h3, lo3;
                split_bf16(p0, h0, lo0); split_bf16(p1, h1, lo1);
                split_bf16(p2, h2, lo2); split_bf16(p3, h3, lo3);
                ph[jj*2+0] = pack2(h0, h1);   ph[jj*2+1] = pack2(h2, h3);
                pl[jj*2+0] = pack2(lo0, lo1); pl[jj*2+1] = pack2(lo2, lo3);
            }
#pragma unroll
            for (int cj = 0; cj < 4; cj++) {
                unsigned bh[4], bl[4];
                ldsm_x4t(bh, sm_addr(sm+SG_PVH + (kg*16 + ar)*72 + cj*16 + ac));
                ldsm_x4t(bl, sm_addr(sm+SG_PVL + (kg*16 + ar)*72 + cj*16 + ac));
                mma16816(oacc[2*cj],   ph, bh);   mma16816(oacc[2*cj],   ph, bl);
                mma16816(oacc[2*cj],   pl, bh);
                mma16816(oacc[2*cj+1], ph, bh+2); mma16816(oacc[2*cj+1], ph, bl+2);
                mma16816(oacc[2*cj+1], pl, bh+2);
            }
        }
    }

    const float be = beta[0];
#pragma unroll
    for (int j = 0; j < 8; j++) {
        int c = j*8 + cp;
        size_t i0 = ((size_t)bt*N_ + gr)*C_ + c;
        size_t i8 = ((size_t)bt*N_ + gr + 8)*C_ + c;
        out[i0]   += be * fmaxf(oacc[j][0], 0.f);
        out[i0+1] += be * fmaxf(oacc[j][1], 0.f);
        out[i8]   += be * fmaxf(oacc[j][2], 0.f);
        out[i8+1] += be * fmaxf(oacc[j][3], 0.f);
    }
}

// ======================= dual GEMM, 2 bt per block ==========================
#define OD_A1H 0
#define OD_A1L 9216
#define OD_A2H 18432
#define OD_A2L 27648
#define OD_B0H 36864
#define OD_B0L 41472
#define OD_B1H 46080
#define OD_B1L 50688
#define SMD_BYTES (55296 * 2)   // 108 KB

__global__ void __launch_bounds__(256) k_dual_mma(const float* __restrict__ gamma,
                                                  float* __restrict__ out) {
    extern __shared__ __nv_bfloat16 sm[];
    const int bt0 = blockIdx.y * 2, r0 = blockIdx.x * 128;
    const int tid = threadIdx.x, wid = tid >> 5, lane = tid & 31;
    const int m_base = (wid >> 1) * 32, n_base = (wid & 1) * 32;
    float acc1[2][2][4][4] = {}, acc2[2][2][4][4] = {};
    for (int ch = 0; ch < 16; ch++) {
        int ko = ch * 64;
        stage<8>(sm+OD_A1H, 72, g_A_hi   + (size_t)r0*N_ + ko, N_, 128);
        stage<8>(sm+OD_A1L, 72, g_A_lo   + (size_t)r0*N_ + ko, N_, 128);
        stage<8>(sm+OD_A2H, 72, g_sup_hi + (size_t)r0*N_ + ko, N_, 128);
        stage<8>(sm+OD_A2L, 72, g_sup_lo + (size_t)r0*N_ + ko, N_, 128);
        stage<8>(sm+OD_B0H, 72, g_x_hi + ((size_t)bt0*N_ + ko)*C_, C_, 64);
        stage<8>(sm+OD_B0L, 72, g_x_lo + ((size_t)bt0*N_ + ko)*C_, C_, 64);
        stage<8>(sm+OD_B1H, 72, g_x_hi + ((size_t)(bt0+1)*N_ + ko)*C_, C_, 64);
        stage<8>(sm+OD_B1L, 72, g_x_lo + ((size_t)(bt0+1)*N_ + ko)*C_, C_, 64);
        __syncthreads();
        warp_mma<2>(acc1[0], sm+OD_A1H, sm+OD_A1L, 72, sm+OD_B0H, sm+OD_B0L, 72,
                    m_base, n_base, lane);
        warp_mma<2>(acc2[0], sm+OD_A2H, sm+OD_A2L, 72, sm+OD_B0H, sm+OD_B0L, 72,
                    m_base, n_base, lane);
        warp_mma<2>(acc1[1], sm+OD_A1H, sm+OD_A1L, 72, sm+OD_B1H, sm+OD_B1L, 72,
                    m_base, n_base, lane);
        warp_mma<2>(acc2[1], sm+OD_A2H, sm+OD_A2L, 72, sm+OD_B1H, sm+OD_B1L, 72,
                    m_base, n_base, lane);
        __syncthreads();
    }
    const float g = gamma[0];
#pragma unroll
    for (int q = 0; q < 2; q++) {
        int bt = bt0 + q;
#pragma unroll
        for (int mi = 0; mi < 2; mi++)
#pragma unroll
            for (int j = 0; j < 4; j++) {
                int r = r0 + m_base + mi*16 + (lane >> 2);
                int c = n_base + j*8 + (lane & 3)*2;
                size_t i0 = ((size_t)bt*N_ + r)*C_ + c;
                size_t i8 = ((size_t)bt*N_ + r + 8)*C_ + c;
                out[i0]   = g * fmaxf(acc1[q][mi][j][0], 0.f);
                out[i0+1] = g * fmaxf(acc1[q][mi][j][1], 0.f);
                out[i8]   = g * fmaxf(acc1[q][mi][j][2], 0.f);
                out[i8+1] = g * fmaxf(acc1[q][mi][j][3], 0.f);
                g_xg[i0]   = acc2[q][mi][j][0];
                g_xg[i0+1] = acc2[q][mi][j][1];
                g_xg[i8]   = acc2[q][mi][j][2];
                g_xg[i8+1] = acc2[q][mi][j][3];
            }
    }
}

// ======================= bias (fp32, split-K) ===============================
__global__ void k_bias_part(const float* __restrict__ bp) {
    __shared__ float As[16][68];
    __shared__ float Bs[16][68];
    int tid = threadIdx.x, tx = tid & 15, ty = tid >> 4;
    int m0 = blockIdx.x * 64, kb = blockIdx.y * 128;
    float acc[4][4] = {};
    for (int k0 = kb; k0 < kb + 128; k0 += 16) {
#pragma unroll
        for (int e = tid; e < 1024; e += 256) {
            int mm = e >> 4, kk = e & 15;
            As[kk][mm] = g_supports[(size_t)(m0+mm)*N_ + k0 + kk];
        }
#pragma unroll
        for (int e = tid; e < 1024; e += 256) {
            int kk = e >> 6, nn = e & 63;
            Bs[kk][nn] = bp[(size_t)(k0+kk)*C_ + nn];
        }
        __syncthreads();
#pragma unroll
        for (int k = 0; k < 16; k++) {
            float4 ra = *(const float4*)&As[k][ty<<2];
            float4 rb = *(const float4*)&Bs[k][tx<<2];
            float a[4] = {ra.x, ra.y, ra.z, ra.w};
            float b[4] = {rb.x, rb.y, rb.z, rb.w};
#pragma unroll
            for (int i = 0; i < 4; i++)
#pragma unroll
                for (int j = 0; j < 4; j++) acc[i][j] += a[i]*b[j];
        }
        __syncthreads();
    }
    float* dst = g_bias_part + (size_t)blockIdx.y * N_ * C_;
#pragma unroll
    for (int i = 0; i < 4; i++)
#pragma unroll
        for (int j = 0; j < 4; j++)
            dst[(size_t)(m0+(ty<<2)+i)*C_ + (tx<<2) + j] = acc[i][j];
}
__global__ void k_bias_red() {
    int i = blockIdx.x * 256 + threadIdx.x;
    float s = 0.f;
#pragma unroll
    for (int c = 0; c < 8; c++) s += g_bias_part[(size_t)c*N_*C_ + i];
    g_bias[i] = s;
}

// ---------------- gconv: out += alpha*relu(xg[:,n,:] @ W[n] + bias[n]) ------
__global__ void k_gconv(const float* __restrict__ alpha,
                        float* __restrict__ out) {
    int n = blockIdx.x, tid = threadIdx.x;
    __shared__ float Ws[64*64];
    __shared__ float Xs[96][64];
    __shared__ float bs[64];
#pragma unroll
    for (int e = tid; e < 4096; e += 256) Ws[e] = g_weights[(size_t)n*4096 + e];
    if (tid < 64) bs[tid] = g_bias[(size_t)n*64 + tid];
#pragma unroll
    for (int e = tid; e < 96*64; e += 256) {
        int r = e >> 6, c = e & 63;
        Xs[r][c] = g_xg[((size_t)r*N_ + n)*C_ + c];
    }
    __syncthreads();
    float al = alpha[0];
    int o = tid & 63, rg = tid >> 6;
    for (int r = rg; r < 96; r += 4) {
        float acc = bs[o];
#pragma unroll
        for (int i = 0; i < 64; i++) acc = fmaf(Xs[r][i], Ws[i*64 + o], acc);
        size_t idx = ((size_t)r*N_ + n)*C_ + o;
        out[idx] += al * fmaxf(acc, 0.f);
    }
}

// ======================= launch =============================================
extern "C" void kernel_launch(void* const* d_in, const int* in_sizes, int n_in,
                              void* d_out, int out_size) {
    (void)in_sizes; (void)n_in; (void)out_size;
    const float* x     = (const float*)d_in[0];
    const float* e1    = (const float*)d_in[1];
    const float* e2    = (const float*)d_in[2];
    const float* A_sym = (const float*)d_in[3];
    const float* wp    = (const float*)d_in[4];
    const float* bp    = (const float*)d_in[5];
    const float* alpha = (const float*)d_in[6];
    const float* beta  = (const float*)d_in[7];
    const float* gamma = (const float*)d_in[8];
    float* out = (float*)d_out;

    cudaFuncSetAttribute(k_weights_mma, cudaFuncAttributeMaxDynamicSharedMemorySize, SMW_BYTES);
    cudaFuncSetAttribute(k_score_mma,   cudaFuncAttributeMaxDynamicSharedMemorySize, SMW_BYTES);
    cudaFuncSetAttribute(k_sa_gmem,     cudaFuncAttributeMaxDynamicSharedMemorySize, SMSG_BYTES);
    cudaFuncSetAttribute(k_dual_mma,    cudaFuncAttributeMaxDynamicSharedMemorySize, SMD_BYTES);

    k_supports   <<<dim3(N_/16, N_/16), dim3(16,16)>>>(e1, e2);
    k_softmaxA   <<<N_, 256>>>(A_sym);
    k_cvt_x      <<<dim3(N_/64, BT_), 256>>>(x);
    k_cvt_wp     <<<(1024*4096)/(256*4), 256>>>(wp);
    k_weights_mma<<<dim3(32, 8), 256, SMW_BYTES>>>();
    k_bias_part  <<<dim3(N_/64, 8), 256>>>(bp);
    k_bias_red   <<<(N_*C_)/256, 256>>>();
    k_score_mma  <<<dim3(8, 8, BT_), 256, SMW_BYTES>>>();
    k_lse        <<<(B_*N_*N_)/256, 256>>>();
    k_dual_mma   <<<dim3(8, BT_/2), 256, SMD_BYTES>>>(gamma, out);
    k_sa_gmem    <<<dim3(8, BT_), 256, SMSG_BYTES>>>(beta, out);
    k_gconv      <<<N_, 256>>>(alpha, out);
}

// round 12
// speedup vs baseline: 1.3513x; 1.3513x over previous
#include <cuda_runtime.h>
#include <cuda_bf16.h>
#include <math.h>
#include <stdint.h>

#define B_  8
#define T_  12
#define N_  1024
#define C_  64
#define D_  10
#define BT_ (B_*T_)   // 96

// ======================= mma.sync / ldmatrix helpers ========================
__device__ __forceinline__ uint32_t sm_addr(const void* p) {
    return (uint32_t)__cvta_generic_to_shared(p);
}
__device__ __forceinline__ void ldsm_x4(unsigned* r, uint32_t a) {
    asm volatile("ldmatrix.sync.aligned.m8n8.x4.shared.b16 {%0,%1,%2,%3}, [%4];"
                 : "=r"(r[0]), "=r"(r[1]), "=r"(r[2]), "=r"(r[3]) : "r"(a));
}
__device__ __forceinline__ void ldsm_x4t(unsigned* r, uint32_t a) {
    asm volatile("ldmatrix.sync.aligned.m8n8.x4.trans.shared.b16 {%0,%1,%2,%3}, [%4];"
                 : "=r"(r[0]), "=r"(r[1]), "=r"(r[2]), "=r"(r[3]) : "r"(a));
}
__device__ __forceinline__ void mma16816(float* d, const unsigned* a, const unsigned* b) {
    asm volatile("mma.sync.aligned.m16n8k16.row.col.f32.bf16.bf16.f32 "
                 "{%0,%1,%2,%3}, {%4,%5,%6,%7}, {%8,%9}, {%0,%1,%2,%3};"
                 : "+f"(d[0]), "+f"(d[1]), "+f"(d[2]), "+f"(d[3])
                 : "r"(a[0]), "r"(a[1]), "r"(a[2]), "r"(a[3]),
                   "r"(b[0]), "r"(b[1]));
}
__device__ __forceinline__ void split_bf16(float v, __nv_bfloat16& h, __nv_bfloat16& l) {
    h = __float2bfloat16(v);
    l = __float2bfloat16(v - __bfloat162float(h));
}

// ---- cp.async (LDGSTS) staging ----
__device__ __forceinline__ void cp_async16(uint32_t s, const void* g) {
    asm volatile("cp.async.cg.shared.global [%0], [%1], 16;" :: "r"(s), "l"(g));
}
#define CP_COMMIT()  asm volatile("cp.async.commit_group;")
#define CP_WAIT1()   asm volatile("cp.async.wait_group 1;")
#define CP_WAIT0()   asm volatile("cp.async.wait_group 0;")

// stage rows x (COLS8*8) bf16 tile gmem->smem (sync loads, for non-pipelined)
template<int COLS8>
__device__ __forceinline__ void stage(__nv_bfloat16* s, int pitch,
                                      const __nv_bfloat16* __restrict__ g,
                                      size_t gstride, int rows) {
    int tot = rows * COLS8;
    for (int i = threadIdx.x; i < tot; i += blockDim.x) {
        int r = i / COLS8, c = (i % COLS8) * 8;
        *(uint4*)(s + r*pitch + c) = *(const uint4*)(g + (size_t)r*gstride + c);
    }
}
// async variant
template<int COLS8>
__device__ __forceinline__ void stage_async(__nv_bfloat16* s, int pitch,
                                            const __nv_bfloat16* __restrict__ g,
                                            size_t gstride, int rows) {
    int tot = rows * COLS8;
    for (int i = threadIdx.x; i < tot; i += blockDim.x) {
        int r = i / COLS8, c = (i % COLS8) * 8;
        cp_async16(sm_addr(s + r*pitch + c), g + (size_t)r*gstride + c);
    }
}

// warp-level split-bf16 MMA over one 64-K chunk (MI m-tiles x 32 n)
template<int MI>
__device__ __forceinline__ void warp_mma(float (&acc)[MI][4][4],
        const __nv_bfloat16* Ah, const __nv_bfloat16* Al, int pa,
        const __nv_bfloat16* Bh, const __nv_bfloat16* Bl, int pb,
        int m_base, int n_base, int lane) {
    const int ar = lane & 15, ac = (lane >> 4) * 8;
#pragma unroll
    for (int ks = 0; ks < 4; ks++) {
        unsigned ah[MI][4], al[MI][4], bh[2][4], bl[2][4];
#pragma unroll
        for (int mi = 0; mi < MI; mi++) {
            int off = (m_base + mi*16 + ar)*pa + ks*16 + ac;
            ldsm_x4(ah[mi], sm_addr(Ah + off));
            ldsm_x4(al[mi], sm_addr(Al + off));
        }
#pragma unroll
        for (int njp = 0; njp < 2; njp++) {
            int off = (ks*16 + ar)*pb + n_base + njp*16 + ac;
            ldsm_x4t(bh[njp], sm_addr(Bh + off));
            ldsm_x4t(bl[njp], sm_addr(Bl + off));
        }
#pragma unroll
        for (int mi = 0; mi < MI; mi++)
#pragma unroll
            for (int j = 0; j < 4; j++) {
                const unsigned* ph = &bh[j>>1][(j&1)*2];
                const unsigned* pl = &bl[j>>1][(j&1)*2];
                mma16816(acc[mi][j], ah[mi], ph);
                mma16816(acc[mi][j], ah[mi], pl);
                mma16816(acc[mi][j], al[mi], ph);
            }
    }
}

// ======================= scratch globals ====================================
__device__ float         g_supports[N_*N_];
__device__ __nv_bfloat16 g_sup_hi[N_*N_], g_sup_lo[N_*N_];
__device__ __nv_bfloat16 g_A_hi[N_*N_],   g_A_lo[N_*N_];
__device__ __nv_bfloat16 g_x_hi[(size_t)BT_*N_*C_],  g_x_lo[(size_t)BT_*N_*C_];
__device__ __nv_bfloat16 g_xT_hi[(size_t)BT_*C_*N_], g_xT_lo[(size_t)BT_*C_*N_];
__device__ __nv_bfloat16 g_wp_hi[(size_t)1024*4096], g_wp_lo[(size_t)1024*4096];
__device__ float         g_weights[N_*C_*C_];
__device__ float         g_bias[N_*C_];
__device__ float         g_bias_part[8*N_*C_];
__device__ float         g_score[(size_t)BT_*N_*N_];
__device__ __nv_bfloat16 g_P_hi[(size_t)BT_*N_*N_], g_P_lo[(size_t)BT_*N_*N_];
__device__ float         g_xg[(size_t)BT_*N_*C_];

// ======================= small kernels ======================================
__global__ void k_supports(const float* __restrict__ e1,
                           const float* __restrict__ e2) {
    int j = blockIdx.x * 16 + threadIdx.x;
    int i = blockIdx.y * 16 + threadIdx.y;
    float d = 0.f;
#pragma unroll
    for (int k = 0; k < D_; k++)
        d += e1[i*D_+k]*e2[j*D_+k] - e2[i*D_+k]*e1[j*D_+k];
    float v = fmaxf(tanhf(d), 0.f);
    if (i == j) v += 1.f;
    g_supports[i*N_ + j] = v;
    __nv_bfloat16 h, l; split_bf16(v, h, l);
    g_sup_hi[i*N_ + j] = h; g_sup_lo[i*N_ + j] = l;
}

__global__ void k_softmaxA(const float* __restrict__ A_sym) {
    int row = blockIdx.x, t = threadIdx.x;
    const float* r = A_sym + (size_t)row * N_;
    __shared__ float red[256];
    float vals[4]; float m = -3.4e38f;
#pragma unroll
    for (int q = 0; q < 4; q++) { vals[q] = r[t + q*256]; m = fmaxf(m, vals[q]); }
    red[t] = m; __syncthreads();
    for (int s = 128; s > 0; s >>= 1) { if (t < s) red[t] = fmaxf(red[t], red[t+s]); __syncthreads(); }
    m = red[0]; __syncthreads();
    float sum = 0.f;
#pragma unroll
    for (int q = 0; q < 4; q++) { vals[q] = expf(vals[q] - m); sum += vals[q]; }
    red[t] = sum; __syncthreads();
    for (int s = 128; s > 0; s >>= 1) { if (t < s) red[t] += red[t+s]; __syncthreads(); }
    float inv = 1.f / red[0];
#pragma unroll
    for (int q = 0; q < 4; q++) {
        float v = vals[q] * inv;
        __nv_bfloat16 h, l; split_bf16(v, h, l);
        size_t idx = (size_t)row*N_ + t + q*256;
        g_A_hi[idx] = h; g_A_lo[idx] = l;
    }
}

__global__ void k_cvt_x(const float* __restrict__ x) {
    int bt = blockIdx.y, n0 = blockIdx.x * 64;
    __shared__ float tbuf[64][65];
    int tid = threadIdx.x;
    for (int e = tid; e < 4096; e += 256) {
        int n = e >> 6, c = e & 63;
        float v = x[((size_t)bt*N_ + n0 + n)*C_ + c];
        tbuf[n][c] = v;
        __nv_bfloat16 h, l; split_bf16(v, h, l);
        size_t idx = ((size_t)bt*N_ + n0 + n)*C_ + c;
        g_x_hi[idx] = h; g_x_lo[idx] = l;
    }
    __syncthreads();
    for (int e = tid; e < 4096; e += 256) {
        int c = e >> 6, n = e & 63;
        float v = tbuf[n][c];
        __nv_bfloat16 h, l; split_bf16(v, h, l);
        size_t idx = ((size_t)bt*C_ + c)*N_ + n0 + n;
        g_xT_hi[idx] = h; g_xT_lo[idx] = l;
    }
}

__global__ void k_cvt_wp(const float* __restrict__ wp) {
    size_t i = ((size_t)blockIdx.x*256 + threadIdx.x)*4;
    float4 v = *(const float4*)(wp + i);
    __nv_bfloat16 h, l;
    split_bf16(v.x, h, l); g_wp_hi[i+0] = h; g_wp_lo[i+0] = l;
    split_bf16(v.y, h, l); g_wp_hi[i+1] = h; g_wp_lo[i+1] = l;
    split_bf16(v.z, h, l); g_wp_hi[i+2] = h; g_wp_lo[i+2] = l;
    split_bf16(v.w, h, l); g_wp_hi[i+3] = h; g_wp_lo[i+3] = l;
}

// ======================= weights GEMM (double-buffered) =====================
// per-stage elem offsets: A 128x72 (hi/lo), B 64x136 (hi/lo)
#define W_AH 0
#define W_AL 9216
#define W_BH 18432
#define W_BL 27136
#define W_STG 35840
#define SMW_BYTES (2 * W_STG * 2)   // 143360

__global__ void __launch_bounds__(256) k_weights_mma(const float* __restrict__ dummy) {
    extern __shared__ __nv_bfloat16 sm[];
    const int n0 = blockIdx.y * 128, io0 = blockIdx.x * 128;
    const int tid = threadIdx.x, wid = tid >> 5, lane = tid & 31;
    const int m_base = (wid >> 2) * 64, n_base = (wid & 3) * 32;
    (void)dummy; (void)tid;

    auto issue = [&](int ch) {
        __nv_bfloat16* s = sm + (ch & 1) * W_STG;
        int ko = ch * 64;
        stage_async<8> (s+W_AH,  72, g_sup_hi + (size_t)n0*N_ + ko, N_, 128);
        stage_async<8> (s+W_AL,  72, g_sup_lo + (size_t)n0*N_ + ko, N_, 128);
        stage_async<16>(s+W_BH, 136, g_wp_hi + (size_t)ko*4096 + io0, 4096, 64);
        stage_async<16>(s+W_BL, 136, g_wp_lo + (size_t)ko*4096 + io0, 4096, 64);
        CP_COMMIT();
    };

    float acc[4][4][4] = {};
    issue(0);
    for (int ch = 0; ch < 16; ch++) {
        if (ch < 15) { issue(ch + 1); CP_WAIT1(); } else { CP_WAIT0(); }
        __syncthreads();
        __nv_bfloat16* s = sm + (ch & 1) * W_STG;
        warp_mma<4>(acc, s+W_AH, s+W_AL, 72, s+W_BH, s+W_BL, 136,
                    m_base, n_base, lane);
        __syncthreads();
    }
#pragma unroll
    for (int mi = 0; mi < 4; mi++)
#pragma unroll
        for (int j = 0; j < 4; j++) {
            int r = n0 + m_base + mi*16 + (lane >> 2);
            int c = io0 + n_base + j*8 + (lane & 3)*2;
            g_weights[(size_t)r*4096 + c]       = acc[mi][j][0];
            g_weights[(size_t)r*4096 + c + 1]   = acc[mi][j][1];
            g_weights[(size_t)(r+8)*4096 + c]   = acc[mi][j][2];
            g_weights[(size_t)(r+8)*4096 + c+1] = acc[mi][j][3];
        }
}

// ======================= score GEMM (single K-chunk, as R8) =================
#define SMSC_BYTES (W_STG * 2)   // 71680

__global__ void __launch_bounds__(256) k_score_mma() {
    extern __shared__ __nv_bfloat16 sm[];
    const int bt = blockIdx.z, n0 = blockIdx.y * 128, m0 = blockIdx.x * 128;
    const int tid = threadIdx.x, wid = tid >> 5, lane = tid & 31;
    const int m_base = (wid >> 2) * 64, n_base = (wid & 3) * 32;
    (void)tid;
    float acc[4][4][4] = {};
    stage<8> (sm+W_AH,  72, g_x_hi + ((size_t)bt*N_ + n0)*C_, C_, 128);
    stage<8> (sm+W_AL,  72, g_x_lo + ((size_t)bt*N_ + n0)*C_, C_, 128);
    stage<16>(sm+W_BH, 136, g_xT_hi + (size_t)bt*C_*N_ + m0, N_, 64);
    stage<16>(sm+W_BL, 136, g_xT_lo + (size_t)bt*C_*N_ + m0, N_, 64);
    __syncthreads();
    warp_mma<4>(acc, sm+W_AH, sm+W_AL, 72, sm+W_BH, sm+W_BL, 136,
                m_base, n_base, lane);
    float* S = g_score + (size_t)bt*N_*N_;
#pragma unroll
    for (int mi = 0; mi < 4; mi++)
#pragma unroll
        for (int j = 0; j < 4; j++) {
            int r = n0 + m_base + mi*16 + (lane >> 2);
            int c = m0 + n_base + j*8 + (lane & 3)*2;
            S[(size_t)r*N_ + c]       = acc[mi][j][0];
            S[(size_t)r*N_ + c + 1]   = acc[mi][j][1];
            S[(size_t)(r+8)*N_ + c]   = acc[mi][j][2];
            S[(size_t)(r+8)*N_ + c+1] = acc[mi][j][3];
        }
}

// ======================= softmax over T, writes split-bf16 P ================
__global__ void k_softmax_t() {
    size_t idx = (size_t)blockIdx.x * blockDim.x + threadIdx.x;
    int b = (int)(idx >> 20);
    size_t r = idx & ((size_t)N_*N_ - 1);
    size_t base = (size_t)b * T_ * N_ * N_ + r;
    float v[T_]; float m = -3.4e38f;
#pragma unroll
    for (int t = 0; t < T_; t++) {
        v[t] = g_score[base + (size_t)t * N_ * N_];
        m = fmaxf(m, v[t]);
    }
    float sum = 0.f;
#pragma unroll
    for (int t = 0; t < T_; t++) { v[t] = __expf(v[t] - m); sum += v[t]; }
    float inv = 1.f / sum;
#pragma unroll
    for (int t = 0; t < T_; t++) {
        float p = v[t] * inv;
        __nv_bfloat16 h, l; split_bf16(p, h, l);
        size_t o = base + (size_t)t * N_ * N_;
        g_P_hi[o] = h; g_P_lo[o] = l;
    }
}

// ======================= sa: out += beta*relu(P @ X), double-buffered =======
// per-stage: P 128x72 hi/lo + X 64x72 hi/lo
#define S_PH 0
#define S_PL 9216
#define S_XH 18432
#define S_XL 23040
#define S_STG 27648
#define SMS_BYTES (2 * S_STG * 2)   // 110592

__global__ void __launch_bounds__(256) k_sa_mma(const float* __restrict__ beta,
                                                float* __restrict__ out) {
    extern __shared__ __nv_bfloat16 sm[];
    const int bt = blockIdx.y, r0 = blockIdx.x * 128;
    const int tid = threadIdx.x, wid = tid >> 5, lane = tid & 31;
    const int m_base = (wid >> 1) * 32, n_base = (wid & 1) * 32;
    (void)tid;

    auto issue = [&](int ch) {
        __nv_bfloat16* s = sm + (ch & 1) * S_STG;
        int ko = ch * 64;
        stage_async<8>(s+S_PH, 72, g_P_hi + ((size_t)bt*N_ + r0)*N_ + ko, N_, 128);
        stage_async<8>(s+S_PL, 72, g_P_lo + ((size_t)bt*N_ + r0)*N_ + ko, N_, 128);
        stage_async<8>(s+S_XH, 72, g_x_hi + ((size_t)bt*N_ + ko)*C_, C_, 64);
        stage_async<8>(s+S_XL, 72, g_x_lo + ((size_t)bt*N_ + ko)*C_, C_, 64);
        CP_COMMIT();
    };

    float acc[2][4][4] = {};
    issue(0);
    for (int ch = 0; ch < 16; ch++) {
        if (ch < 15) { issue(ch + 1); CP_WAIT1(); } else { CP_WAIT0(); }
        __syncthreads();
        __nv_bfloat16* s = sm + (ch & 1) * S_STG;
        warp_mma<2>(acc, s+S_PH, s+S_PL, 72, s+S_XH, s+S_XL, 72,
                    m_base, n_base, lane);
        __syncthreads();
    }
    const float be = beta[0];
#pragma unroll
    for (int mi = 0; mi < 2; mi++)
#pragma unroll
        for (int j = 0; j < 4; j++) {
            int r = r0 + m_base + mi*16 + (lane >> 2);
            int c = n_base + j*8 + (lane & 3)*2;
            size_t i0 = ((size_t)bt*N_ + r)*C_ + c;
            size_t i8 = ((size_t)bt*N_ + r + 8)*C_ + c;
            out[i0]   += be * fmaxf(acc[mi][j][0], 0.f);
            out[i0+1] += be * fmaxf(acc[mi][j][1], 0.f);
            out[i8]   += be * fmaxf(acc[mi][j][2], 0.f);
            out[i8+1] += be * fmaxf(acc[mi][j][3], 0.f);
        }
}

// ======================= dual GEMM: 2 bt per block, double-buffered =========
#define D_A1H 0
#define D_A1L 9216
#define D_A2H 18432
#define D_A2L 27648
#define D_B0H 36864
#define D_B0L 41472
#define D_B1H 46080
#define D_B1L 50688
#define D_STG 55296
#define SMD_BYTES (2 * D_STG * 2)   // 221184

__global__ void __launch_bounds__(256) k_dual_mma(const float* __restrict__ gamma,
                                                  float* __restrict__ out) {
    extern __shared__ __nv_bfloat16 sm[];
    const int bt0 = blockIdx.y * 2, r0 = blockIdx.x * 128;
    const int tid = threadIdx.x, wid = tid >> 5, lane = tid & 31;
    const int m_base = (wid >> 1) * 32, n_base = (wid & 1) * 32;
    (void)tid;

    auto issue = [&](int ch) {
        __nv_bfloat16* s = sm + (ch & 1) * D_STG;
        int ko = ch * 64;
        stage_async<8>(s+D_A1H, 72, g_A_hi   + (size_t)r0*N_ + ko, N_, 128);
        stage_async<8>(s+D_A1L, 72, g_A_lo   + (size_t)r0*N_ + ko, N_, 128);
        stage_async<8>(s+D_A2H, 72, g_sup_hi + (size_t)r0*N_ + ko, N_, 128);
        stage_async<8>(s+D_A2L, 72, g_sup_lo + (size_t)r0*N_ + ko, N_, 128);
        stage_async<8>(s+D_B0H, 72, g_x_hi + ((size_t)bt0*N_ + ko)*C_, C_, 64);
        stage_async<8>(s+D_B0L, 72, g_x_lo + ((size_t)bt0*N_ + ko)*C_, C_, 64);
        stage_async<8>(s+D_B1H, 72, g_x_hi + ((size_t)(bt0+1)*N_ + ko)*C_, C_, 64);
        stage_async<8>(s+D_B1L, 72, g_x_lo + ((size_t)(bt0+1)*N_ + ko)*C_, C_, 64);
        CP_COMMIT();
    };

    float acc1[2][2][4][4] = {}, acc2[2][2][4][4] = {};
    issue(0);
    for (int ch = 0; ch < 16; ch++) {
        if (ch < 15) { issue(ch + 1); CP_WAIT1(); } else { CP_WAIT0(); }
        __syncthreads();
        __nv_bfloat16* s = sm + (ch & 1) * D_STG;
        warp_mma<2>(acc1[0], s+D_A1H, s+D_A1L, 72, s+D_B0H, s+D_B0L, 72,
                    m_base, n_base, lane);
        warp_mma<2>(acc2[0], s+D_A2H, s+D_A2L, 72, s+D_B0H, s+D_B0L, 72,
                    m_base, n_base, lane);
        warp_mma<2>(acc1[1], s+D_A1H, s+D_A1L, 72, s+D_B1H, s+D_B1L, 72,
                    m_base, n_base, lane);
        warp_mma<2>(acc2[1], s+D_A2H, s+D_A2L, 72, s+D_B1H, s+D_B1L, 72,
                    m_base, n_base, lane);
        __syncthreads();
    }
    const float g = gamma[0];
#pragma unroll
    for (int q = 0; q < 2; q++) {
        int bt = bt0 + q;
#pragma unroll
        for (int mi = 0; mi < 2; mi++)
#pragma unroll
            for (int j = 0; j < 4; j++) {
                int r = r0 + m_base + mi*16 + (lane >> 2);
                int c = n_base + j*8 + (lane & 3)*2;
                size_t i0 = ((size_t)bt*N_ + r)*C_ + c;
                size_t i8 = ((size_t)bt*N_ + r + 8)*C_ + c;
                out[i0]   = g * fmaxf(acc1[q][mi][j][0], 0.f);
                out[i0+1] = g * fmaxf(acc1[q][mi][j][1], 0.f);
                out[i8]   = g * fmaxf(acc1[q][mi][j][2], 0.f);
                out[i8+1] = g * fmaxf(acc1[q][mi][j][3], 0.f);
                g_xg[i0]   = acc2[q][mi][j][0];
                g_xg[i0+1] = acc2[q][mi][j][1];
                g_xg[i8]   = acc2[q][mi][j][2];
                g_xg[i8+1] = acc2[q][mi][j][3];
            }
    }
}

// ======================= bias (fp32, split-K) ===============================
__global__ void k_bias_part(const float* __restrict__ bp) {
    __shared__ float As[16][68];
    __shared__ float Bs[16][68];
    int tid = threadIdx.x, tx = tid & 15, ty = tid >> 4;
    int m0 = blockIdx.x * 64, kb = blockIdx.y * 128;
    float acc[4][4] = {};
    for (int k0 = kb; k0 < kb + 128; k0 += 16) {
#pragma unroll
        for (int e = tid; e < 1024; e += 256) {
            int mm = e >> 4, kk = e & 15;
            As[kk][mm] = g_supports[(size_t)(m0+mm)*N_ + k0 + kk];
        }
#pragma unroll
        for (int e = tid; e < 1024; e += 256) {
            int kk = e >> 6, nn = e & 63;
            Bs[kk][nn] = bp[(size_t)(k0+kk)*C_ + nn];
        }
        __syncthreads();
#pragma unroll
        for (int k = 0; k < 16; k++) {
            float4 ra = *(const float4*)&As[k][ty<<2];
            float4 rb = *(const float4*)&Bs[k][tx<<2];
            float a[4] = {ra.x, ra.y, ra.z, ra.w};
            float b[4] = {rb.x, rb.y, rb.z, rb.w};
#pragma unroll
            for (int i = 0; i < 4; i++)
#pragma unroll
                for (int j = 0; j < 4; j++) acc[i][j] += a[i]*b[j];
        }
        __syncthreads();
    }
    float* dst = g_bias_part + (size_t)blockIdx.y * N_ * C_;
#pragma unroll
    for (int i = 0; i < 4; i++)
#pragma unroll
        for (int j = 0; j < 4; j++)
            dst[(size_t)(m0+(ty<<2)+i)*C_ + (tx<<2) + j] = acc[i][j];
}
__global__ void k_bias_red() {
    int i = blockIdx.x * 256 + threadIdx.x;
    float s = 0.f;
#pragma unroll
    for (int c = 0; c < 8; c++) s += g_bias_part[(size_t)c*N_*C_ + i];
    g_bias[i] = s;
}

// ---------------- gconv: out += alpha*relu(xg[:,n,:] @ W[n] + bias[n]) ------
__global__ void k_gconv(const float* __restrict__ alpha,
                        float* __restrict__ out) {
    int n = blockIdx.x, tid = threadIdx.x;
    __shared__ float Ws[64*64];
    __shared__ float Xs[96][64];
    __shared__ float bs[64];
#pragma unroll
    for (int e = tid; e < 4096; e += 256) Ws[e] = g_weights[(size_t)n*4096 + e];
    if (tid < 64) bs[tid] = g_bias[(size_t)n*64 + tid];
#pragma unroll
    for (int e = tid; e < 96*64; e += 256) {
        int r = e >> 6, c = e & 63;
        Xs[r][c] = g_xg[((size_t)r*N_ + n)*C_ + c];
    }
    __syncthreads();
    float al = alpha[0];
    int o = tid & 63, rg = tid >> 6;
    for (int r = rg; r < 96; r += 4) {
        float acc = bs[o];
#pragma unroll
        for (int i = 0; i < 64; i++) acc = fmaf(Xs[r][i], Ws[i*64 + o], acc);
        size_t idx = ((size_t)r*N_ + n)*C_ + o;
        out[idx] += al * fmaxf(acc, 0.f);
    }
}

// ======================= launch =============================================
extern "C" void kernel_launch(void* const* d_in, const int* in_sizes, int n_in,
                              void* d_out, int out_size) {
    (void)in_sizes; (void)n_in; (void)out_size;
    const float* x     = (const float*)d_in[0];
    const float* e1    = (const float*)d_in[1];
    const float* e2    = (const float*)d_in[2];
    const float* A_sym = (const float*)d_in[3];
    const float* wp    = (const float*)d_in[4];
    const float* bp    = (const float*)d_in[5];
    const float* alpha = (const float*)d_in[6];
    const float* beta  = (const float*)d_in[7];
    const float* gamma = (const float*)d_in[8];
    float* out = (float*)d_out;

    cudaFuncSetAttribute(k_weights_mma, cudaFuncAttributeMaxDynamicSharedMemorySize, SMW_BYTES);
    cudaFuncSetAttribute(k_score_mma,   cudaFuncAttributeMaxDynamicSharedMemorySize, SMSC_BYTES);
    cudaFuncSetAttribute(k_sa_mma,      cudaFuncAttributeMaxDynamicSharedMemorySize, SMS_BYTES);
    cudaFuncSetAttribute(k_dual_mma,    cudaFuncAttributeMaxDynamicSharedMemorySize, SMD_BYTES);

    k_supports   <<<dim3(N_/16, N_/16), dim3(16,16)>>>(e1, e2);
    k_softmaxA   <<<N_, 256>>>(A_sym);
    k_cvt_x      <<<dim3(N_/64, BT_), 256>>>(x);
    k_cvt_wp     <<<(1024*4096)/(256*4), 256>>>(wp);
    k_weights_mma<<<dim3(32, 8), 256, SMW_BYTES>>>(nullptr);
    k_bias_part  <<<dim3(N_/64, 8), 256>>>(bp);
    k_bias_red   <<<(N_*C_)/256, 256>>>();
    k_score_mma  <<<dim3(8, 8, BT_), 256, SMSC_BYTES>>>();
    k_softmax_t  <<<(B_*N_*N_)/256, 256>>>();
    k_dual_mma   <<<dim3(8, BT_/2), 256, SMD_BYTES>>>(gamma, out);
    k_sa_mma     <<<dim3(8, BT_), 256, SMS_BYTES>>>(beta, out);
    k_gconv      <<<N_, 256>>>(alpha, out);
}

// round 13
// speedup vs baseline: 1.3898x; 1.0285x over previous
#include <cuda_runtime.h>
#include <cuda_bf16.h>
#include <math.h>
#include <stdint.h>

#define B_  8
#define T_  12
#define N_  1024
#define C_  64
#define D_  10
#define BT_ (B_*T_)   // 96

// ======================= mma.sync / ldmatrix helpers ========================
__device__ __forceinline__ uint32_t sm_addr(const void* p) {
    return (uint32_t)__cvta_generic_to_shared(p);
}
__device__ __forceinline__ void ldsm_x4(unsigned* r, uint32_t a) {
    asm volatile("ldmatrix.sync.aligned.m8n8.x4.shared.b16 {%0,%1,%2,%3}, [%4];"
                 : "=r"(r[0]), "=r"(r[1]), "=r"(r[2]), "=r"(r[3]) : "r"(a));
}
__device__ __forceinline__ void ldsm_x4t(unsigned* r, uint32_t a) {
    asm volatile("ldmatrix.sync.aligned.m8n8.x4.trans.shared.b16 {%0,%1,%2,%3}, [%4];"
                 : "=r"(r[0]), "=r"(r[1]), "=r"(r[2]), "=r"(r[3]) : "r"(a));
}
__device__ __forceinline__ void mma16816(float* d, const unsigned* a, const unsigned* b) {
    asm volatile("mma.sync.aligned.m16n8k16.row.col.f32.bf16.bf16.f32 "
                 "{%0,%1,%2,%3}, {%4,%5,%6,%7}, {%8,%9}, {%0,%1,%2,%3};"
                 : "+f"(d[0]), "+f"(d[1]), "+f"(d[2]), "+f"(d[3])
                 : "r"(a[0]), "r"(a[1]), "r"(a[2]), "r"(a[3]),
                   "r"(b[0]), "r"(b[1]));
}
__device__ __forceinline__ void split_bf16(float v, __nv_bfloat16& h, __nv_bfloat16& l) {
    h = __float2bfloat16(v);
    l = __float2bfloat16(v - __bfloat162float(h));
}

// ---- cp.async (LDGSTS) staging ----
__device__ __forceinline__ void cp_async16(uint32_t s, const void* g) {
    asm volatile("cp.async.cg.shared.global [%0], [%1], 16;" :: "r"(s), "l"(g));
}
#define CP_COMMIT()  asm volatile("cp.async.commit_group;")
#define CP_WAIT1()   asm volatile("cp.async.wait_group 1;")
#define CP_WAIT0()   asm volatile("cp.async.wait_group 0;")

// stage rows x (COLS8*8) bf16 tile gmem->smem (sync loads)
template<int COLS8>
__device__ __forceinline__ void stage(__nv_bfloat16* s, int pitch,
                                      const __nv_bfloat16* __restrict__ g,
                                      size_t gstride, int rows) {
    int tot = rows * COLS8;
    for (int i = threadIdx.x; i < tot; i += blockDim.x) {
        int r = i / COLS8, c = (i % COLS8) * 8;
        *(uint4*)(s + r*pitch + c) = *(const uint4*)(g + (size_t)r*gstride + c);
    }
}
// async variant
template<int COLS8>
__device__ __forceinline__ void stage_async(__nv_bfloat16* s, int pitch,
                                            const __nv_bfloat16* __restrict__ g,
                                            size_t gstride, int rows) {
    int tot = rows * COLS8;
    for (int i = threadIdx.x; i < tot; i += blockDim.x) {
        int r = i / COLS8, c = (i % COLS8) * 8;
        cp_async16(sm_addr(s + r*pitch + c), g + (size_t)r*gstride + c);
    }
}

// warp-level split-bf16 MMA over one 64-K chunk (MI m-tiles x 32 n)
template<int MI>
__device__ __forceinline__ void warp_mma(float (&acc)[MI][4][4],
        const __nv_bfloat16* Ah, const __nv_bfloat16* Al, int pa,
        const __nv_bfloat16* Bh, const __nv_bfloat16* Bl, int pb,
        int m_base, int n_base, int lane) {
    const int ar = lane & 15, ac = (lane >> 4) * 8;
#pragma unroll
    for (int ks = 0; ks < 4; ks++) {
        unsigned ah[MI][4], al[MI][4], bh[2][4], bl[2][4];
#pragma unroll
        for (int mi = 0; mi < MI; mi++) {
            int off = (m_base + mi*16 + ar)*pa + ks*16 + ac;
            ldsm_x4(ah[mi], sm_addr(Ah + off));
            ldsm_x4(al[mi], sm_addr(Al + off));
        }
#pragma unroll
        for (int njp = 0; njp < 2; njp++) {
            int off = (ks*16 + ar)*pb + n_base + njp*16 + ac;
            ldsm_x4t(bh[njp], sm_addr(Bh + off));
            ldsm_x4t(bl[njp], sm_addr(Bl + off));
        }
#pragma unroll
        for (int mi = 0; mi < MI; mi++)
#pragma unroll
            for (int j = 0; j < 4; j++) {
                const unsigned* ph = &bh[j>>1][(j&1)*2];
                const unsigned* pl = &bl[j>>1][(j&1)*2];
                mma16816(acc[mi][j], ah[mi], ph);
                mma16816(acc[mi][j], ah[mi], pl);
                mma16816(acc[mi][j], al[mi], ph);
            }
    }
}

// ======================= scratch globals ====================================
__device__ float         g_supports[N_*N_];
__device__ __nv_bfloat16 g_sup_hi[N_*N_], g_sup_lo[N_*N_];
__device__ __nv_bfloat16 g_A_hi[N_*N_],   g_A_lo[N_*N_];
__device__ __nv_bfloat16 g_x_hi[(size_t)BT_*N_*C_],  g_x_lo[(size_t)BT_*N_*C_];
__device__ __nv_bfloat16 g_xT_hi[(size_t)BT_*C_*N_], g_xT_lo[(size_t)BT_*C_*N_];
__device__ __nv_bfloat16 g_wp_hi[(size_t)1024*4096], g_wp_lo[(size_t)1024*4096];
__device__ float         g_weights[N_*C_*C_];
__device__ float         g_bias[N_*C_];
__device__ float         g_bias_part[8*N_*C_];
__device__ float         g_score[(size_t)BT_*N_*N_];
__device__ __nv_bfloat16 g_P_hi[(size_t)BT_*N_*N_], g_P_lo[(size_t)BT_*N_*N_];
__device__ float         g_xg[(size_t)BT_*N_*C_];

// ======================= small kernels ======================================
__global__ void k_supports(const float* __restrict__ e1,
                           const float* __restrict__ e2) {
    int j = blockIdx.x * 16 + threadIdx.x;
    int i = blockIdx.y * 16 + threadIdx.y;
    float d = 0.f;
#pragma unroll
    for (int k = 0; k < D_; k++)
        d += e1[i*D_+k]*e2[j*D_+k] - e2[i*D_+k]*e1[j*D_+k];
    float v = fmaxf(tanhf(d), 0.f);
    if (i == j) v += 1.f;
    g_supports[i*N_ + j] = v;
    __nv_bfloat16 h, l; split_bf16(v, h, l);
    g_sup_hi[i*N_ + j] = h; g_sup_lo[i*N_ + j] = l;
}

__global__ void k_softmaxA(const float* __restrict__ A_sym) {
    int row = blockIdx.x, t = threadIdx.x;
    const float* r = A_sym + (size_t)row * N_;
    __shared__ float red[256];
    float vals[4]; float m = -3.4e38f;
#pragma unroll
    for (int q = 0; q < 4; q++) { vals[q] = r[t + q*256]; m = fmaxf(m, vals[q]); }
    red[t] = m; __syncthreads();
    for (int s = 128; s > 0; s >>= 1) { if (t < s) red[t] = fmaxf(red[t], red[t+s]); __syncthreads(); }
    m = red[0]; __syncthreads();
    float sum = 0.f;
#pragma unroll
    for (int q = 0; q < 4; q++) { vals[q] = expf(vals[q] - m); sum += vals[q]; }
    red[t] = sum; __syncthreads();
    for (int s = 128; s > 0; s >>= 1) { if (t < s) red[t] += red[t+s]; __syncthreads(); }
    float inv = 1.f / red[0];
#pragma unroll
    for (int q = 0; q < 4; q++) {
        float v = vals[q] * inv;
        __nv_bfloat16 h, l; split_bf16(v, h, l);
        size_t idx = (size_t)row*N_ + t + q*256;
        g_A_hi[idx] = h; g_A_lo[idx] = l;
    }
}

__global__ void k_cvt_x(const float* __restrict__ x) {
    int bt = blockIdx.y, n0 = blockIdx.x * 64;
    __shared__ float tbuf[64][65];
    int tid = threadIdx.x;
    for (int e = tid; e < 4096; e += 256) {
        int n = e >> 6, c = e & 63;
        float v = x[((size_t)bt*N_ + n0 + n)*C_ + c];
        tbuf[n][c] = v;
        __nv_bfloat16 h, l; split_bf16(v, h, l);
        size_t idx = ((size_t)bt*N_ + n0 + n)*C_ + c;
        g_x_hi[idx] = h; g_x_lo[idx] = l;
    }
    __syncthreads();
    for (int e = tid; e < 4096; e += 256) {
        int c = e >> 6, n = e & 63;
        float v = tbuf[n][c];
        __nv_bfloat16 h, l; split_bf16(v, h, l);
        size_t idx = ((size_t)bt*C_ + c)*N_ + n0 + n;
        g_xT_hi[idx] = h; g_xT_lo[idx] = l;
    }
}

__global__ void k_cvt_wp(const float* __restrict__ wp) {
    size_t i = ((size_t)blockIdx.x*256 + threadIdx.x)*4;
    float4 v = *(const float4*)(wp + i);
    __nv_bfloat16 h, l;
    split_bf16(v.x, h, l); g_wp_hi[i+0] = h; g_wp_lo[i+0] = l;
    split_bf16(v.y, h, l); g_wp_hi[i+1] = h; g_wp_lo[i+1] = l;
    split_bf16(v.z, h, l); g_wp_hi[i+2] = h; g_wp_lo[i+2] = l;
    split_bf16(v.w, h, l); g_wp_hi[i+3] = h; g_wp_lo[i+3] = l;
}

// ======================= weights GEMM (double-buffered) =====================
#define W_AH 0
#define W_AL 9216
#define W_BH 18432
#define W_BL 27136
#define W_STG 35840
#define SMW_BYTES (2 * W_STG * 2)   // 143360

__global__ void __launch_bounds__(256) k_weights_mma() {
    extern __shared__ __nv_bfloat16 sm[];
    const int n0 = blockIdx.y * 128, io0 = blockIdx.x * 128;
    const int wid = threadIdx.x >> 5, lane = threadIdx.x & 31;
    const int m_base = (wid >> 2) * 64, n_base = (wid & 3) * 32;

    auto issue = [&](int ch) {
        __nv_bfloat16* s = sm + (ch & 1) * W_STG;
        int ko = ch * 64;
        stage_async<8> (s+W_AH,  72, g_sup_hi + (size_t)n0*N_ + ko, N_, 128);
        stage_async<8> (s+W_AL,  72, g_sup_lo + (size_t)n0*N_ + ko, N_, 128);
        stage_async<16>(s+W_BH, 136, g_wp_hi + (size_t)ko*4096 + io0, 4096, 64);
        stage_async<16>(s+W_BL, 136, g_wp_lo + (size_t)ko*4096 + io0, 4096, 64);
        CP_COMMIT();
    };

    float acc[4][4][4] = {};
    issue(0);
    for (int ch = 0; ch < 16; ch++) {
        if (ch < 15) { issue(ch + 1); CP_WAIT1(); } else { CP_WAIT0(); }
        __syncthreads();
        __nv_bfloat16* s = sm + (ch & 1) * W_STG;
        warp_mma<4>(acc, s+W_AH, s+W_AL, 72, s+W_BH, s+W_BL, 136,
                    m_base, n_base, lane);
        __syncthreads();
    }
#pragma unroll
    for (int mi = 0; mi < 4; mi++)
#pragma unroll
        for (int j = 0; j < 4; j++) {
            int r = n0 + m_base + mi*16 + (lane >> 2);
            int c = io0 + n_base + j*8 + (lane & 3)*2;
            g_weights[(size_t)r*4096 + c]       = acc[mi][j][0];
            g_weights[(size_t)r*4096 + c + 1]   = acc[mi][j][1];
            g_weights[(size_t)(r+8)*4096 + c]   = acc[mi][j][2];
            g_weights[(size_t)(r+8)*4096 + c+1] = acc[mi][j][3];
        }
}

// ======================= score GEMM (single K-chunk) ========================
#define SMSC_BYTES (W_STG * 2)   // 71680

__global__ void __launch_bounds__(256) k_score_mma() {
    extern __shared__ __nv_bfloat16 sm[];
    const int bt = blockIdx.z, n0 = blockIdx.y * 128, m0 = blockIdx.x * 128;
    const int wid = threadIdx.x >> 5, lane = threadIdx.x & 31;
    const int m_base = (wid >> 2) * 64, n_base = (wid & 3) * 32;
    float acc[4][4][4] = {};
    stage<8> (sm+W_AH,  72, g_x_hi + ((size_t)bt*N_ + n0)*C_, C_, 128);
    stage<8> (sm+W_AL,  72, g_x_lo + ((size_t)bt*N_ + n0)*C_, C_, 128);
    stage<16>(sm+W_BH, 136, g_xT_hi + (size_t)bt*C_*N_ + m0, N_, 64);
    stage<16>(sm+W_BL, 136, g_xT_lo + (size_t)bt*C_*N_ + m0, N_, 64);
    __syncthreads();
    warp_mma<4>(acc, sm+W_AH, sm+W_AL, 72, sm+W_BH, sm+W_BL, 136,
                m_base, n_base, lane);
    float* S = g_score + (size_t)bt*N_*N_;
#pragma unroll
    for (int mi = 0; mi < 4; mi++)
#pragma unroll
        for (int j = 0; j < 4; j++) {
            int r = n0 + m_base + mi*16 + (lane >> 2);
            int c = m0 + n_base + j*8 + (lane & 3)*2;
            S[(size_t)r*N_ + c]       = acc[mi][j][0];
            S[(size_t)r*N_ + c + 1]   = acc[mi][j][1];
            S[(size_t)(r+8)*N_ + c]   = acc[mi][j][2];
            S[(size_t)(r+8)*N_ + c+1] = acc[mi][j][3];
        }
}

// ======================= softmax over T, writes split-bf16 P ================
__global__ void k_softmax_t() {
    size_t idx = (size_t)blockIdx.x * blockDim.x + threadIdx.x;
    int b = (int)(idx >> 20);
    size_t r = idx & ((size_t)N_*N_ - 1);
    size_t base = (size_t)b * T_ * N_ * N_ + r;
    float v[T_]; float m = -3.4e38f;
#pragma unroll
    for (int t = 0; t < T_; t++) {
        v[t] = g_score[base + (size_t)t * N_ * N_];
        m = fmaxf(m, v[t]);
    }
    float sum = 0.f;
#pragma unroll
    for (int t = 0; t < T_; t++) { v[t] = __expf(v[t] - m); sum += v[t]; }
    float inv = 1.f / sum;
#pragma unroll
    for (int t = 0; t < T_; t++) {
        float p = v[t] * inv;
        __nv_bfloat16 h, l; split_bf16(p, h, l);
        size_t o = base + (size_t)t * N_ * N_;
        g_P_hi[o] = h; g_P_lo[o] = l;
    }
}

// ======================= sa: out += beta*relu(P @ X), double-buffered =======
#define S_PH 0
#define S_PL 9216
#define S_XH 18432
#define S_XL 23040
#define S_STG 27648
#define SMS_BYTES (2 * S_STG * 2)   // 110592

__global__ void __launch_bounds__(256) k_sa_mma(const float* __restrict__ beta,
                                                float* __restrict__ out) {
    extern __shared__ __nv_bfloat16 sm[];
    const int bt = blockIdx.y, r0 = blockIdx.x * 128;
    const int wid = threadIdx.x >> 5, lane = threadIdx.x & 31;
    const int m_base = (wid >> 1) * 32, n_base = (wid & 1) * 32;

    auto issue = [&](int ch) {
        __nv_bfloat16* s = sm + (ch & 1) * S_STG;
        int ko = ch * 64;
        stage_async<8>(s+S_PH, 72, g_P_hi + ((size_t)bt*N_ + r0)*N_ + ko, N_, 128);
        stage_async<8>(s+S_PL, 72, g_P_lo + ((size_t)bt*N_ + r0)*N_ + ko, N_, 128);
        stage_async<8>(s+S_XH, 72, g_x_hi + ((size_t)bt*N_ + ko)*C_, C_, 64);
        stage_async<8>(s+S_XL, 72, g_x_lo + ((size_t)bt*N_ + ko)*C_, C_, 64);
        CP_COMMIT();
    };

    float acc[2][4][4] = {};
    issue(0);
    for (int ch = 0; ch < 16; ch++) {
        if (ch < 15) { issue(ch + 1); CP_WAIT1(); } else { CP_WAIT0(); }
        __syncthreads();
        __nv_bfloat16* s = sm + (ch & 1) * S_STG;
        warp_mma<2>(acc, s+S_PH, s+S_PL, 72, s+S_XH, s+S_XL, 72,
                    m_base, n_base, lane);
        __syncthreads();
    }
    const float be = beta[0];
#pragma unroll
    for (int mi = 0; mi < 2; mi++)
#pragma unroll
        for (int j = 0; j < 4; j++) {
            int r = r0 + m_base + mi*16 + (lane >> 2);
            int c = n_base + j*8 + (lane & 3)*2;
            size_t i0 = ((size_t)bt*N_ + r)*C_ + c;
            size_t i8 = ((size_t)bt*N_ + r + 8)*C_ + c;
            out[i0]   += be * fmaxf(acc[mi][j][0], 0.f);
            out[i0+1] += be * fmaxf(acc[mi][j][1], 0.f);
            out[i8]   += be * fmaxf(acc[mi][j][2], 0.f);
            out[i8+1] += be * fmaxf(acc[mi][j][3], 0.f);
        }
}

// ======================= dual GEMM: 2 bt per block, double-buffered =========
#define D_A1H 0
#define D_A1L 9216
#define D_A2H 18432
#define D_A2L 27648
#define D_B0H 36864
#define D_B0L 41472
#define D_B1H 46080
#define D_B1L 50688
#define D_STG 55296
#define SMD_BYTES (2 * D_STG * 2)   // 221184

__global__ void __launch_bounds__(256) k_dual_mma(const float* __restrict__ gamma,
                                                  float* __restrict__ out) {
    extern __shared__ __nv_bfloat16 sm[];
    const int bt0 = blockIdx.y * 2, r0 = blockIdx.x * 128;
    const int wid = threadIdx.x >> 5, lane = threadIdx.x & 31;
    const int m_base = (wid >> 1) * 32, n_base = (wid & 1) * 32;

    auto issue = [&](int ch) {
        __nv_bfloat16* s = sm + (ch & 1) * D_STG;
        int ko = ch * 64;
        stage_async<8>(s+D_A1H, 72, g_A_hi   + (size_t)r0*N_ + ko, N_, 128);
        stage_async<8>(s+D_A1L, 72, g_A_lo   + (size_t)r0*N_ + ko, N_, 128);
        stage_async<8>(s+D_A2H, 72, g_sup_hi + (size_t)r0*N_ + ko, N_, 128);
        stage_async<8>(s+D_A2L, 72, g_sup_lo + (size_t)r0*N_ + ko, N_, 128);
        stage_async<8>(s+D_B0H, 72, g_x_hi + ((size_t)bt0*N_ + ko)*C_, C_, 64);
        stage_async<8>(s+D_B0L, 72, g_x_lo + ((size_t)bt0*N_ + ko)*C_, C_, 64);
        stage_async<8>(s+D_B1H, 72, g_x_hi + ((size_t)(bt0+1)*N_ + ko)*C_, C_, 64);
        stage_async<8>(s+D_B1L, 72, g_x_lo + ((size_t)(bt0+1)*N_ + ko)*C_, C_, 64);
        CP_COMMIT();
    };

    float acc1[2][2][4][4] = {}, acc2[2][2][4][4] = {};
    issue(0);
    for (int ch = 0; ch < 16; ch++) {
        if (ch < 15) { issue(ch + 1); CP_WAIT1(); } else { CP_WAIT0(); }
        __syncthreads();
        __nv_bfloat16* s = sm + (ch & 1) * D_STG;
        warp_mma<2>(acc1[0], s+D_A1H, s+D_A1L, 72, s+D_B0H, s+D_B0L, 72,
                    m_base, n_base, lane);
        warp_mma<2>(acc2[0], s+D_A2H, s+D_A2L, 72, s+D_B0H, s+D_B0L, 72,
                    m_base, n_base, lane);
        warp_mma<2>(acc1[1], s+D_A1H, s+D_A1L, 72, s+D_B1H, s+D_B1L, 72,
                    m_base, n_base, lane);
        warp_mma<2>(acc2[1], s+D_A2H, s+D_A2L, 72, s+D_B1H, s+D_B1L, 72,
                    m_base, n_base, lane);
        __syncthreads();
    }
    const float g = gamma[0];
#pragma unroll
    for (int q = 0; q < 2; q++) {
        int bt = bt0 + q;
#pragma unroll
        for (int mi = 0; mi < 2; mi++)
#pragma unroll
            for (int j = 0; j < 4; j++) {
                int r = r0 + m_base + mi*16 + (lane >> 2);
                int c = n_base + j*8 + (lane & 3)*2;
                size_t i0 = ((size_t)bt*N_ + r)*C_ + c;
                size_t i8 = ((size_t)bt*N_ + r + 8)*C_ + c;
                out[i0]   = g * fmaxf(acc1[q][mi][j][0], 0.f);
                out[i0+1] = g * fmaxf(acc1[q][mi][j][1], 0.f);
                out[i8]   = g * fmaxf(acc1[q][mi][j][2], 0.f);
                out[i8+1] = g * fmaxf(acc1[q][mi][j][3], 0.f);
                g_xg[i0]   = acc2[q][mi][j][0];
                g_xg[i0+1] = acc2[q][mi][j][1];
                g_xg[i8]   = acc2[q][mi][j][2];
                g_xg[i8+1] = acc2[q][mi][j][3];
            }
    }
}

// ======================= bias (fp32, split-K) ===============================
__global__ void k_bias_part(const float* __restrict__ bp) {
    __shared__ float As[16][68];
    __shared__ float Bs[16][68];
    int tid = threadIdx.x, tx = tid & 15, ty = tid >> 4;
    int m0 = blockIdx.x * 64, kb = blockIdx.y * 128;
    float acc[4][4] = {};
    for (int k0 = kb; k0 < kb + 128; k0 += 16) {
#pragma unroll
        for (int e = tid; e < 1024; e += 256) {
            int mm = e >> 4, kk = e & 15;
            As[kk][mm] = g_supports[(size_t)(m0+mm)*N_ + k0 + kk];
        }
#pragma unroll
        for (int e = tid; e < 1024; e += 256) {
            int kk = e >> 6, nn = e & 63;
            Bs[kk][nn] = bp[(size_t)(k0+kk)*C_ + nn];
        }
        __syncthreads();
#pragma unroll
        for (int k = 0; k < 16; k++) {
            float4 ra = *(const float4*)&As[k][ty<<2];
            float4 rb = *(const float4*)&Bs[k][tx<<2];
            float a[4] = {ra.x, ra.y, ra.z, ra.w};
            float b[4] = {rb.x, rb.y, rb.z, rb.w};
#pragma unroll
            for (int i = 0; i < 4; i++)
#pragma unroll
                for (int j = 0; j < 4; j++) acc[i][j] += a[i]*b[j];
        }
        __syncthreads();
    }
    float* dst = g_bias_part + (size_t)blockIdx.y * N_ * C_;
#pragma unroll
    for (int i = 0; i < 4; i++)
#pragma unroll
        for (int j = 0; j < 4; j++)
            dst[(size_t)(m0+(ty<<2)+i)*C_ + (tx<<2) + j] = acc[i][j];
}
__global__ void k_bias_red() {
    int i = blockIdx.x * 256 + threadIdx.x;
    float s = 0.f;
#pragma unroll
    for (int c = 0; c < 8; c++) s += g_bias_part[(size_t)c*N_*C_ + i];
    g_bias[i] = s;
}

// ---------------- gconv: out += alpha*relu(xg[:,n,:] @ W[n] + bias[n]) ------
__global__ void k_gconv(const float* __restrict__ alpha,
                        float* __restrict__ out) {
    int n = blockIdx.x, tid = threadIdx.x;
    __shared__ float Ws[64*64];
    __shared__ float Xs[96][64];
    __shared__ float bs[64];
#pragma unroll
    for (int e = tid; e < 4096; e += 256) Ws[e] = g_weights[(size_t)n*4096 + e];
    if (tid < 64) bs[tid] = g_bias[(size_t)n*64 + tid];
#pragma unroll
    for (int e = tid; e < 96*64; e += 256) {
        int r = e >> 6, c = e & 63;
        Xs[r][c] = g_xg[((size_t)r*N_ + n)*C_ + c];
    }
    __syncthreads();
    float al = alpha[0];
    int o = tid & 63, rg = tid >> 6;
    for (int r = rg; r < 96; r += 4) {
        float acc = bs[o];
#pragma unroll
        for (int i = 0; i < 64; i++) acc = fmaf(Xs[r][i], Ws[i*64 + o], acc);
        size_t idx = ((size_t)r*N_ + n)*C_ + o;
        out[idx] += al * fmaxf(acc, 0.f);
    }
}

// ======================= launch =============================================
extern "C" void kernel_launch(void* const* d_in, const int* in_sizes, int n_in,
                              void* d_out, int out_size) {
    (void)in_sizes; (void)n_in; (void)out_size;
    const float* x     = (const float*)d_in[0];
    const float* e1    = (const float*)d_in[1];
    const float* e2    = (const float*)d_in[2];
    const float* A_sym = (const float*)d_in[3];
    const float* wp    = (const float*)d_in[4];
    const float* bp    = (const float*)d_in[5];
    const float* alpha = (const float*)d_in[6];
    const float* beta  = (const float*)d_in[7];
    const float* gamma = (const float*)d_in[8];
    float* out = (float*)d_out;

    // side stream + fork/join events, created once (first call is the
    // non-captured correctness run; subsequent captured calls reuse them).
    static cudaStream_t s2 = nullptr;
    static cudaEvent_t evFork = nullptr, evSup = nullptr, evW = nullptr;
    if (s2 == nullptr) {
        cudaStreamCreateWithFlags(&s2, cudaStreamNonBlocking);
        cudaEventCreateWithFlags(&evFork, cudaEventDisableTiming);
        cudaEventCreateWithFlags(&evSup,  cudaEventDisableTiming);
        cudaEventCreateWithFlags(&evW,    cudaEventDisableTiming);
        cudaFuncSetAttribute(k_weights_mma, cudaFuncAttributeMaxDynamicSharedMemorySize, SMW_BYTES);
        cudaFuncSetAttribute(k_score_mma,   cudaFuncAttributeMaxDynamicSharedMemorySize, SMSC_BYTES);
        cudaFuncSetAttribute(k_sa_mma,      cudaFuncAttributeMaxDynamicSharedMemorySize, SMS_BYTES);
        cudaFuncSetAttribute(k_dual_mma,    cudaFuncAttributeMaxDynamicSharedMemorySize, SMD_BYTES);
    }

    // ---- fork: chain A (cvt_wp -> weights -> bias) on s2 ----
    cudaEventRecord(evFork, 0);
    cudaStreamWaitEvent(s2, evFork, 0);
    k_cvt_wp<<<(1024*4096)/(256*4), 256, 0, s2>>>(wp);

    // main: supports (needed by chain A's weights/bias)
    k_supports<<<dim3(N_/16, N_/16), dim3(16,16)>>>(e1, e2);
    cudaEventRecord(evSup, 0);
    cudaStreamWaitEvent(s2, evSup, 0);

    k_weights_mma<<<dim3(32, 8), 256, SMW_BYTES, s2>>>();
    k_bias_part  <<<dim3(N_/64, 8), 256, 0, s2>>>(bp);
    k_bias_red   <<<(N_*C_)/256, 256, 0, s2>>>();
    cudaEventRecord(evW, s2);

    // main: chain B (critical path)
    k_softmaxA <<<N_, 256>>>(A_sym);
    k_cvt_x    <<<dim3(N_/64, BT_), 256>>>(x);
    k_score_mma<<<dim3(8, 8, BT_), 256, SMSC_BYTES>>>();
    k_softmax_t<<<(B_*N_*N_)/256, 256>>>();
    k_dual_mma <<<dim3(8, BT_/2), 256, SMD_BYTES>>>(gamma, out);
    k_sa_mma   <<<dim3(8, BT_), 256, SMS_BYTES>>>(beta, out);

    // ---- join: gconv needs weights+bias (chain A) and xg (dual) ----
    cudaStreamWaitEvent(0, evW, 0);
    k_gconv<<<N_, 256>>>(alpha, out);
}

// round 14
// speedup vs baseline: 1.7501x; 1.2592x over previous
#include <cuda_runtime.h>
#include <cuda_fp16.h>
#include <math.h>
#include <stdint.h>

#define B_  8
#define T_  12
#define N_  1024
#define C_  64
#define D_  10
#define BT_ (B_*T_)   // 96

// ======================= mma.sync / ldmatrix helpers ========================
__device__ __forceinline__ uint32_t sm_addr(const void* p) {
    return (uint32_t)__cvta_generic_to_shared(p);
}
__device__ __forceinline__ void ldsm_x4(unsigned* r, uint32_t a) {
    asm volatile("ldmatrix.sync.aligned.m8n8.x4.shared.b16 {%0,%1,%2,%3}, [%4];"
                 : "=r"(r[0]), "=r"(r[1]), "=r"(r[2]), "=r"(r[3]) : "r"(a));
}
__device__ __forceinline__ void ldsm_x4t(unsigned* r, uint32_t a) {
    asm volatile("ldmatrix.sync.aligned.m8n8.x4.trans.shared.b16 {%0,%1,%2,%3}, [%4];"
                 : "=r"(r[0]), "=r"(r[1]), "=r"(r[2]), "=r"(r[3]) : "r"(a));
}
__device__ __forceinline__ void mma16816(float* d, const unsigned* a, const unsigned* b) {
    asm volatile("mma.sync.aligned.m16n8k16.row.col.f32.f16.f16.f32 "
                 "{%0,%1,%2,%3}, {%4,%5,%6,%7}, {%8,%9}, {%0,%1,%2,%3};"
                 : "+f"(d[0]), "+f"(d[1]), "+f"(d[2]), "+f"(d[3])
                 : "r"(a[0]), "r"(a[1]), "r"(a[2]), "r"(a[3]),
                   "r"(b[0]), "r"(b[1]));
}
__device__ __forceinline__ void split_f16(float v, __half& h, __half& l) {
    h = __float2half_rn(v);
    l = __float2half_rn(v - __half2float(h));
}

// ---- cp.async (LDGSTS) staging ----
__device__ __forceinline__ void cp_async16(uint32_t s, const void* g) {
    asm volatile("cp.async.cg.shared.global [%0], [%1], 16;" :: "r"(s), "l"(g));
}
#define CP_COMMIT()  asm volatile("cp.async.commit_group;")
#define CP_WAIT1()   asm volatile("cp.async.wait_group 1;")
#define CP_WAIT0()   asm volatile("cp.async.wait_group 0;")

// stage rows x (COLS8*8) f16 tile gmem->smem (sync loads)
template<int COLS8>
__device__ __forceinline__ void stage(__half* s, int pitch,
                                      const __half* __restrict__ g,
                                      size_t gstride, int rows) {
    int tot = rows * COLS8;
    for (int i = threadIdx.x; i < tot; i += blockDim.x) {
        int r = i / COLS8, c = (i % COLS8) * 8;
        *(uint4*)(s + r*pitch + c) = *(const uint4*)(g + (size_t)r*gstride + c);
    }
}
// async variant
template<int COLS8>
__device__ __forceinline__ void stage_async(__half* s, int pitch,
                                            const __half* __restrict__ g,
                                            size_t gstride, int rows) {
    int tot = rows * COLS8;
    for (int i = threadIdx.x; i < tot; i += blockDim.x) {
        int r = i / COLS8, c = (i % COLS8) * 8;
        cp_async16(sm_addr(s + r*pitch + c), g + (size_t)r*gstride + c);
    }
}

// 3-term split MMA (accuracy-critical; both operands split)
template<int MI>
__device__ __forceinline__ void warp_mma3(float (&acc)[MI][4][4],
        const __half* Ah, const __half* Al, int pa,
        const __half* Bh, const __half* Bl, int pb,
        int m_base, int n_base, int lane) {
    const int ar = lane & 15, ac = (lane >> 4) * 8;
#pragma unroll
    for (int ks = 0; ks < 4; ks++) {
        unsigned ah[MI][4], al[MI][4], bh[2][4], bl[2][4];
#pragma unroll
        for (int mi = 0; mi < MI; mi++) {
            int off = (m_base + mi*16 + ar)*pa + ks*16 + ac;
            ldsm_x4(ah[mi], sm_addr(Ah + off));
            ldsm_x4(al[mi], sm_addr(Al + off));
        }
#pragma unroll
        for (int njp = 0; njp < 2; njp++) {
            int off = (ks*16 + ar)*pb + n_base + njp*16 + ac;
            ldsm_x4t(bh[njp], sm_addr(Bh + off));
            ldsm_x4t(bl[njp], sm_addr(Bl + off));
        }
#pragma unroll
        for (int mi = 0; mi < MI; mi++)
#pragma unroll
            for (int j = 0; j < 4; j++) {
                const unsigned* ph = &bh[j>>1][(j&1)*2];
                const unsigned* pl = &bl[j>>1][(j&1)*2];
                mma16816(acc[mi][j], ah[mi], ph);
                mma16816(acc[mi][j], ah[mi], pl);
                mma16816(acc[mi][j], al[mi], ph);
            }
    }
}

// 2-term split MMA: acc += Ah*(Bh+Bl). Error ~ Al*B ~ 2^-12 relative.
template<int MI>
__device__ __forceinline__ void warp_mma2(float (&acc)[MI][4][4],
        const __half* Ah, int pa,
        const __half* Bh, const __half* Bl, int pb,
        int m_base, int n_base, int lane) {
    const int ar = lane & 15, ac = (lane >> 4) * 8;
#pragma unroll
    for (int ks = 0; ks < 4; ks++) {
        unsigned ah[MI][4], bh[2][4], bl[2][4];
#pragma unroll
        for (int mi = 0; mi < MI; mi++) {
            int off = (m_base + mi*16 + ar)*pa + ks*16 + ac;
            ldsm_x4(ah[mi], sm_addr(Ah + off));
        }
#pragma unroll
        for (int njp = 0; njp < 2; njp++) {
            int off = (ks*16 + ar)*pb + n_base + njp*16 + ac;
            ldsm_x4t(bh[njp], sm_addr(Bh + off));
            ldsm_x4t(bl[njp], sm_addr(Bl + off));
        }
#pragma unroll
        for (int mi = 0; mi < MI; mi++)
#pragma unroll
            for (int j = 0; j < 4; j++) {
                const unsigned* ph = &bh[j>>1][(j&1)*2];
                const unsigned* pl = &bl[j>>1][(j&1)*2];
                mma16816(acc[mi][j], ah[mi], ph);
                mma16816(acc[mi][j], ah[mi], pl);
            }
    }
}

// ======================= scratch globals ====================================
__device__ float  g_supports[N_*N_];
__device__ __half g_sup_h[N_*N_];
__device__ __half g_A_h[N_*N_];
__device__ __half g_x_hi[(size_t)BT_*N_*C_],  g_x_lo[(size_t)BT_*N_*C_];
__device__ __half g_xT_hi[(size_t)BT_*C_*N_], g_xT_lo[(size_t)BT_*C_*N_];
__device__ __half g_wp_hi[(size_t)1024*4096], g_wp_lo[(size_t)1024*4096];
__device__ float  g_weights[N_*C_*C_];
__device__ float  g_bias[N_*C_];
__device__ float  g_bias_part[8*N_*C_];
__device__ float  g_score[(size_t)BT_*N_*N_];
__device__ __half g_P_h[(size_t)BT_*N_*N_];
__device__ float  g_xg[(size_t)BT_*N_*C_];

// ======================= small kernels ======================================
__global__ void k_supports(const float* __restrict__ e1,
                           const float* __restrict__ e2) {
    int j = blockIdx.x * 16 + threadIdx.x;
    int i = blockIdx.y * 16 + threadIdx.y;
    float d = 0.f;
#pragma unroll
    for (int k = 0; k < D_; k++)
        d += e1[i*D_+k]*e2[j*D_+k] - e2[i*D_+k]*e1[j*D_+k];
    float v = fmaxf(tanhf(d), 0.f);
    if (i == j) v += 1.f;
    g_supports[i*N_ + j] = v;
    g_sup_h[i*N_ + j] = __float2half_rn(v);
}

__global__ void k_softmaxA(const float* __restrict__ A_sym) {
    int row = blockIdx.x, t = threadIdx.x;
    const float* r = A_sym + (size_t)row * N_;
    __shared__ float red[256];
    float vals[4]; float m = -3.4e38f;
#pragma unroll
    for (int q = 0; q < 4; q++) { vals[q] = r[t + q*256]; m = fmaxf(m, vals[q]); }
    red[t] = m; __syncthreads();
    for (int s = 128; s > 0; s >>= 1) { if (t < s) red[t] = fmaxf(red[t], red[t+s]); __syncthreads(); }
    m = red[0]; __syncthreads();
    float sum = 0.f;
#pragma unroll
    for (int q = 0; q < 4; q++) { vals[q] = expf(vals[q] - m); sum += vals[q]; }
    red[t] = sum; __syncthreads();
    for (int s = 128; s > 0; s >>= 1) { if (t < s) red[t] += red[t+s]; __syncthreads(); }
    float inv = 1.f / red[0];
#pragma unroll
    for (int q = 0; q < 4; q++)
        g_A_h[(size_t)row*N_ + t + q*256] = __float2half_rn(vals[q] * inv);
}

__global__ void k_cvt_x(const float* __restrict__ x) {
    int bt = blockIdx.y, n0 = blockIdx.x * 64;
    __shared__ float tbuf[64][65];
    int tid = threadIdx.x;
    for (int e = tid; e < 4096; e += 256) {
        int n = e >> 6, c = e & 63;
        float v = x[((size_t)bt*N_ + n0 + n)*C_ + c];
        tbuf[n][c] = v;
        __half h, l; split_f16(v, h, l);
        size_t idx = ((size_t)bt*N_ + n0 + n)*C_ + c;
        g_x_hi[idx] = h; g_x_lo[idx] = l;
    }
    __syncthreads();
    for (int e = tid; e < 4096; e += 256) {
        int c = e >> 6, n = e & 63;
        float v = tbuf[n][c];
        __half h, l; split_f16(v, h, l);
        size_t idx = ((size_t)bt*C_ + c)*N_ + n0 + n;
        g_xT_hi[idx] = h; g_xT_lo[idx] = l;
    }
}

__global__ void k_cvt_wp(const float* __restrict__ wp) {
    size_t i = ((size_t)blockIdx.x*256 + threadIdx.x)*4;
    float4 v = *(const float4*)(wp + i);
    __half h, l;
    split_f16(v.x, h, l); g_wp_hi[i+0] = h; g_wp_lo[i+0] = l;
    split_f16(v.y, h, l); g_wp_hi[i+1] = h; g_wp_lo[i+1] = l;
    split_f16(v.z, h, l); g_wp_hi[i+2] = h; g_wp_lo[i+2] = l;
    split_f16(v.w, h, l); g_wp_hi[i+3] = h; g_wp_lo[i+3] = l;
}

// ======================= weights GEMM (2-MMA, double-buffered) ==============
#define W_AH 0
#define W_BH 9216
#define W_BL 17920
#define W_STG 26624
#define SMW_BYTES (2 * W_STG * 2)   // 106496

__global__ void __launch_bounds__(256) k_weights_mma() {
    extern __shared__ __half sm[];
    const int n0 = blockIdx.y * 128, io0 = blockIdx.x * 128;
    const int wid = threadIdx.x >> 5, lane = threadIdx.x & 31;
    const int m_base = (wid >> 2) * 64, n_base = (wid & 3) * 32;

    auto issue = [&](int ch) {
        __half* s = sm + (ch & 1) * W_STG;
        int ko = ch * 64;
        stage_async<8> (s+W_AH,  72, g_sup_h + (size_t)n0*N_ + ko, N_, 128);
        stage_async<16>(s+W_BH, 136, g_wp_hi + (size_t)ko*4096 + io0, 4096, 64);
        stage_async<16>(s+W_BL, 136, g_wp_lo + (size_t)ko*4096 + io0, 4096, 64);
        CP_COMMIT();
    };

    float acc[4][4][4] = {};
    issue(0);
    for (int ch = 0; ch < 16; ch++) {
        if (ch < 15) { issue(ch + 1); CP_WAIT1(); } else { CP_WAIT0(); }
        __syncthreads();
        __half* s = sm + (ch & 1) * W_STG;
        warp_mma2<4>(acc, s+W_AH, 72, s+W_BH, s+W_BL, 136,
                     m_base, n_base, lane);
        __syncthreads();
    }
#pragma unroll
    for (int mi = 0; mi < 4; mi++)
#pragma unroll
        for (int j = 0; j < 4; j++) {
            int r = n0 + m_base + mi*16 + (lane >> 2);
            int c = io0 + n_base + j*8 + (lane & 3)*2;
            g_weights[(size_t)r*4096 + c]       = acc[mi][j][0];
            g_weights[(size_t)r*4096 + c + 1]   = acc[mi][j][1];
            g_weights[(size_t)(r+8)*4096 + c]   = acc[mi][j][2];
            g_weights[(size_t)(r+8)*4096 + c+1] = acc[mi][j][3];
        }
}

// ======================= score GEMM (3-MMA, single K-chunk) =================
#define SC_AH 0
#define SC_AL 9216
#define SC_BH 18432
#define SC_BL 27136
#define SMSC_BYTES (35840 * 2)   // 71680

__global__ void __launch_bounds__(256) k_score_mma() {
    extern __shared__ __half sm[];
    const int bt = blockIdx.z, n0 = blockIdx.y * 128, m0 = blockIdx.x * 128;
    const int wid = threadIdx.x >> 5, lane = threadIdx.x & 31;
    const int m_base = (wid >> 2) * 64, n_base = (wid & 3) * 32;
    float acc[4][4][4] = {};
    stage<8> (sm+SC_AH,  72, g_x_hi + ((size_t)bt*N_ + n0)*C_, C_, 128);
    stage<8> (sm+SC_AL,  72, g_x_lo + ((size_t)bt*N_ + n0)*C_, C_, 128);
    stage<16>(sm+SC_BH, 136, g_xT_hi + (size_t)bt*C_*N_ + m0, N_, 64);
    stage<16>(sm+SC_BL, 136, g_xT_lo + (size_t)bt*C_*N_ + m0, N_, 64);
    __syncthreads();
    warp_mma3<4>(acc, sm+SC_AH, sm+SC_AL, 72, sm+SC_BH, sm+SC_BL, 136,
                 m_base, n_base, lane);
    float* S = g_score + (size_t)bt*N_*N_;
#pragma unroll
    for (int mi = 0; mi < 4; mi++)
#pragma unroll
        for (int j = 0; j < 4; j++) {
            int r = n0 + m_base + mi*16 + (lane >> 2);
            int c = m0 + n_base + j*8 + (lane & 3)*2;
            S[(size_t)r*N_ + c]       = acc[mi][j][0];
            S[(size_t)r*N_ + c + 1]   = acc[mi][j][1];
            S[(size_t)(r+8)*N_ + c]   = acc[mi][j][2];
            S[(size_t)(r+8)*N_ + c+1] = acc[mi][j][3];
        }
}

// ======================= softmax over T, writes fp16 P ======================
__global__ void k_softmax_t() {
    size_t idx = (size_t)blockIdx.x * blockDim.x + threadIdx.x;
    int b = (int)(idx >> 20);
    size_t r = idx & ((size_t)N_*N_ - 1);
    size_t base = (size_t)b * T_ * N_ * N_ + r;
    float v[T_]; float m = -3.4e38f;
#pragma unroll
    for (int t = 0; t < T_; t++) {
        v[t] = g_score[base + (size_t)t * N_ * N_];
        m = fmaxf(m, v[t]);
    }
    float sum = 0.f;
#pragma unroll
    for (int t = 0; t < T_; t++) { v[t] = __expf(v[t] - m); sum += v[t]; }
    float inv = 1.f / sum;
#pragma unroll
    for (int t = 0; t < T_; t++)
        g_P_h[base + (size_t)t * N_ * N_] = __float2half_rn(v[t] * inv);
}

// ======================= sa: out += beta*relu(P @ X), 2-MMA =================
#define S_PH 0
#define S_XH 9216
#define S_XL 13824
#define S_STG 18432
#define SMS_BYTES (2 * S_STG * 2)   // 73728

__global__ void __launch_bounds__(256) k_sa_mma(const float* __restrict__ beta,
                                                float* __restrict__ out) {
    extern __shared__ __half sm[];
    const int bt = blockIdx.y, r0 = blockIdx.x * 128;
    const int wid = threadIdx.x >> 5, lane = threadIdx.x & 31;
    const int m_base = (wid >> 1) * 32, n_base = (wid & 1) * 32;

    auto issue = [&](int ch) {
        __half* s = sm + (ch & 1) * S_STG;
        int ko = ch * 64;
        stage_async<8>(s+S_PH, 72, g_P_h + ((size_t)bt*N_ + r0)*N_ + ko, N_, 128);
        stage_async<8>(s+S_XH, 72, g_x_hi + ((size_t)bt*N_ + ko)*C_, C_, 64);
        stage_async<8>(s+S_XL, 72, g_x_lo + ((size_t)bt*N_ + ko)*C_, C_, 64);
        CP_COMMIT();
    };

    float acc[2][4][4] = {};
    issue(0);
    for (int ch = 0; ch < 16; ch++) {
        if (ch < 15) { issue(ch + 1); CP_WAIT1(); } else { CP_WAIT0(); }
        __syncthreads();
        __half* s = sm + (ch & 1) * S_STG;
        warp_mma2<2>(acc, s+S_PH, 72, s+S_XH, s+S_XL, 72,
                     m_base, n_base, lane);
        __syncthreads();
    }
    const float be = beta[0];
#pragma unroll
    for (int mi = 0; mi < 2; mi++)
#pragma unroll
        for (int j = 0; j < 4; j++) {
            int r = r0 + m_base + mi*16 + (lane >> 2);
            int c = n_base + j*8 + (lane & 3)*2;
            size_t i0 = ((size_t)bt*N_ + r)*C_ + c;
            size_t i8 = ((size_t)bt*N_ + r + 8)*C_ + c;
            out[i0]   += be * fmaxf(acc[mi][j][0], 0.f);
            out[i0+1] += be * fmaxf(acc[mi][j][1], 0.f);
            out[i8]   += be * fmaxf(acc[mi][j][2], 0.f);
            out[i8+1] += be * fmaxf(acc[mi][j][3], 0.f);
        }
}

// ======================= dual GEMM: 2 bt per block, 2-MMA ====================
#define D_A1H 0
#define D_A2H 9216
#define D_B0H 18432
#define D_B0L 23040
#define D_B1H 27648
#define D_B1L 32256
#define D_STG 36864
#define SMD_BYTES (2 * D_STG * 2)   // 147456

__global__ void __launch_bounds__(256) k_dual_mma(const float* __restrict__ gamma,
                                                  float* __restrict__ out) {
    extern __shared__ __half sm[];
    const int bt0 = blockIdx.y * 2, r0 = blockIdx.x * 128;
    const int wid = threadIdx.x >> 5, lane = threadIdx.x & 31;
    const int m_base = (wid >> 1) * 32, n_base = (wid & 1) * 32;

    auto issue = [&](int ch) {
        __half* s = sm + (ch & 1) * D_STG;
        int ko = ch * 64;
        stage_async<8>(s+D_A1H, 72, g_A_h   + (size_t)r0*N_ + ko, N_, 128);
        stage_async<8>(s+D_A2H, 72, g_sup_h + (size_t)r0*N_ + ko, N_, 128);
        stage_async<8>(s+D_B0H, 72, g_x_hi + ((size_t)bt0*N_ + ko)*C_, C_, 64);
        stage_async<8>(s+D_B0L, 72, g_x_lo + ((size_t)bt0*N_ + ko)*C_, C_, 64);
        stage_async<8>(s+D_B1H, 72, g_x_hi + ((size_t)(bt0+1)*N_ + ko)*C_, C_, 64);
        stage_async<8>(s+D_B1L, 72, g_x_lo + ((size_t)(bt0+1)*N_ + ko)*C_, C_, 64);
        CP_COMMIT();
    };

    float acc1[2][2][4][4] = {}, acc2[2][2][4][4] = {};
    issue(0);
    for (int ch = 0; ch < 16; ch++) {
        if (ch < 15) { issue(ch + 1); CP_WAIT1(); } else { CP_WAIT0(); }
        __syncthreads();
        __half* s = sm + (ch & 1) * D_STG;
        warp_mma2<2>(acc1[0], s+D_A1H, 72, s+D_B0H, s+D_B0L, 72,
                     m_base, n_base, lane);
        warp_mma2<2>(acc2[0], s+D_A2H, 72, s+D_B0H, s+D_B0L, 72,
                     m_base, n_base, lane);
        warp_mma2<2>(acc1[1], s+D_A1H, 72, s+D_B1H, s+D_B1L, 72,
                     m_base, n_base, lane);
        warp_mma2<2>(acc2[1], s+D_A2H, 72, s+D_B1H, s+D_B1L, 72,
                     m_base, n_base, lane);
        __syncthreads();
    }
    const float g = gamma[0];
#pragma unroll
    for (int q = 0; q < 2; q++) {
        int bt = bt0 + q;
#pragma unroll
        for (int mi = 0; mi < 2; mi++)
#pragma unroll
            for (int j = 0; j < 4; j++) {
                int r = r0 + m_base + mi*16 + (lane >> 2);
                int c = n_base + j*8 + (lane & 3)*2;
                size_t i0 = ((size_t)bt*N_ + r)*C_ + c;
                size_t i8 = ((size_t)bt*N_ + r + 8)*C_ + c;
                out[i0]   = g * fmaxf(acc1[q][mi][j][0], 0.f);
                out[i0+1] = g * fmaxf(acc1[q][mi][j][1], 0.f);
                out[i8]   = g * fmaxf(acc1[q][mi][j][2], 0.f);
                out[i8+1] = g * fmaxf(acc1[q][mi][j][3], 0.f);
                g_xg[i0]   = acc2[q][mi][j][0];
                g_xg[i0+1] = acc2[q][mi][j][1];
                g_xg[i8]   = acc2[q][mi][j][2];
                g_xg[i8+1] = acc2[q][mi][j][3];
            }
    }
}

// ======================= bias (fp32, split-K) ===============================
__global__ void k_bias_part(const float* __restrict__ bp) {
    __shared__ float As[16][68];
    __shared__ float Bs[16][68];
    int tid = threadIdx.x, tx = tid & 15, ty = tid >> 4;
    int m0 = blockIdx.x * 64, kb = blockIdx.y * 128;
    float acc[4][4] = {};
    for (int k0 = kb; k0 < kb + 128; k0 += 16) {
#pragma unroll
        for (int e = tid; e < 1024; e += 256) {
            int mm = e >> 4, kk = e & 15;
            As[kk][mm] = g_supports[(size_t)(m0+mm)*N_ + k0 + kk];
        }
#pragma unroll
        for (int e = tid; e < 1024; e += 256) {
            int kk = e >> 6, nn = e & 63;
            Bs[kk][nn] = bp[(size_t)(k0+kk)*C_ + nn];
        }
        __syncthreads();
#pragma unroll
        for (int k = 0; k < 16; k++) {
            float4 ra = *(const float4*)&As[k][ty<<2];
            float4 rb = *(const float4*)&Bs[k][tx<<2];
            float a[4] = {ra.x, ra.y, ra.z, ra.w};
            float b[4] = {rb.x, rb.y, rb.z, rb.w};
#pragma unroll
            for (int i = 0; i < 4; i++)
#pragma unroll
                for (int j = 0; j < 4; j++) acc[i][j] += a[i]*b[j];
        }
        __syncthreads();
    }
    float* dst = g_bias_part + (size_t)blockIdx.y * N_ * C_;
#pragma unroll
    for (int i = 0; i < 4; i++)
#pragma unroll
        for (int j = 0; j < 4; j++)
            dst[(size_t)(m0+(ty<<2)+i)*C_ + (tx<<2) + j] = acc[i][j];
}
__global__ void k_bias_red() {
    int i = blockIdx.x * 256 + threadIdx.x;
    float s = 0.f;
#pragma unroll
    for (int c = 0; c < 8; c++) s += g_bias_part[(size_t)c*N_*C_ + i];
    g_bias[i] = s;
}

// ---------------- gconv: out += alpha*relu(xg[:,n,:] @ W[n] + bias[n]) ------
__global__ void k_gconv(const float* __restrict__ alpha,
                        float* __restrict__ out) {
    int n = blockIdx.x, tid = threadIdx.x;
    __shared__ float Ws[64*64];
    __shared__ float Xs[96][64];
    __shared__ float bs[64];
#pragma unroll
    for (int e = tid; e < 4096; e += 256) Ws[e] = g_weights[(size_t)n*4096 + e];
    if (tid < 64) bs[tid] = g_bias[(size_t)n*64 + tid];
#pragma unroll
    for (int e = tid; e < 96*64; e += 256) {
        int r = e >> 6, c = e & 63;
        Xs[r][c] = g_xg[((size_t)r*N_ + n)*C_ + c];
    }
    __syncthreads();
    float al = alpha[0];
    int o = tid & 63, rg = tid >> 6;
    for (int r = rg; r < 96; r += 4) {
        float acc = bs[o];
#pragma unroll
        for (int i = 0; i < 64; i++) acc = fmaf(Xs[r][i], Ws[i*64 + o], acc);
        size_t idx = ((size_t)r*N_ + n)*C_ + o;
        out[idx] += al * fmaxf(acc, 0.f);
    }
}

// ======================= launch =============================================
extern "C" void kernel_launch(void* const* d_in, const int* in_sizes, int n_in,
                              void* d_out, int out_size) {
    (void)in_sizes; (void)n_in; (void)out_size;
    const float* x     = (const float*)d_in[0];
    const float* e1    = (const float*)d_in[1];
    const float* e2    = (const float*)d_in[2];
    const float* A_sym = (const float*)d_in[3];
    const float* wp    = (const float*)d_in[4];
    const float* bp    = (const float*)d_in[5];
    const float* alpha = (const float*)d_in[6];
    const float* beta  = (const float*)d_in[7];
    const float* gamma = (const float*)d_in[8];
    float* out = (float*)d_out;

    static cudaStream_t s2 = nullptr;
    static cudaEvent_t evFork = nullptr, evSup = nullptr, evW = nullptr;
    if (s2 == nullptr) {
        cudaStreamCreateWithFlags(&s2, cudaStreamNonBlocking);
        cudaEventCreateWithFlags(&evFork, cudaEventDisableTiming);
        cudaEventCreateWithFlags(&evSup,  cudaEventDisableTiming);
        cudaEventCreateWithFlags(&evW,    cudaEventDisableTiming);
        cudaFuncSetAttribute(k_weights_mma, cudaFuncAttributeMaxDynamicSharedMemorySize, SMW_BYTES);
        cudaFuncSetAttribute(k_score_mma,   cudaFuncAttributeMaxDynamicSharedMemorySize, SMSC_BYTES);
        cudaFuncSetAttribute(k_sa_mma,      cudaFuncAttributeMaxDynamicSharedMemorySize, SMS_BYTES);
        cudaFuncSetAttribute(k_dual_mma,    cudaFuncAttributeMaxDynamicSharedMemorySize, SMD_BYTES);
    }

    // ---- fork: chain A (cvt_wp -> weights -> bias) on s2 ----
    cudaEventRecord(evFork, 0);
    cudaStreamWaitEvent(s2, evFork, 0);
    k_cvt_wp<<<(1024*4096)/(256*4), 256, 0, s2>>>(wp);

    k_supports<<<dim3(N_/16, N_/16), dim3(16,16)>>>(e1, e2);
    cudaEventRecord(evSup, 0);
    cudaStreamWaitEvent(s2, evSup, 0);

    k_weights_mma<<<dim3(32, 8), 256, SMW_BYTES, s2>>>();
    k_bias_part  <<<dim3(N_/64, 8), 256, 0, s2>>>(bp);
    k_bias_red   <<<(N_*C_)/256, 256, 0, s2>>>();
    cudaEventRecord(evW, s2);

    // main: chain B (critical path)
    k_softmaxA <<<N_, 256>>>(A_sym);
    k_cvt_x    <<<dim3(N_/64, BT_), 256>>>(x);
    k_score_mma<<<dim3(8, 8, BT_), 256, SMSC_BYTES>>>();
    k_softmax_t<<<(B_*N_*N_)/256, 256>>>();
    k_dual_mma <<<dim3(8, BT_/2), 256, SMD_BYTES>>>(gamma, out);
    k_sa_mma   <<<dim3(8, BT_), 256, SMS_BYTES>>>(beta, out);

    // ---- join: gconv needs weights+bias (chain A) and xg (dual) ----
    cudaStreamWaitEvent(0, evW, 0);
    k_gconv<<<N_, 256>>>(alpha, out);
}

// round 15
// speedup vs baseline: 2.0100x; 1.1485x over previous
#include <cuda_runtime.h>
#include <cuda_fp16.h>
#include <math.h>
#include <stdint.h>

#define B_  8
#define T_  12
#define N_  1024
#define C_  64
#define D_  10
#define BT_ (B_*T_)   // 96

// ======================= mma.sync / ldmatrix helpers ========================
__device__ __forceinline__ uint32_t sm_addr(const void* p) {
    return (uint32_t)__cvta_generic_to_shared(p);
}
__device__ __forceinline__ void ldsm_x4(unsigned* r, uint32_t a) {
    asm volatile("ldmatrix.sync.aligned.m8n8.x4.shared.b16 {%0,%1,%2,%3}, [%4];"
                 : "=r"(r[0]), "=r"(r[1]), "=r"(r[2]), "=r"(r[3]) : "r"(a));
}
__device__ __forceinline__ void ldsm_x4t(unsigned* r, uint32_t a) {
    asm volatile("ldmatrix.sync.aligned.m8n8.x4.trans.shared.b16 {%0,%1,%2,%3}, [%4];"
                 : "=r"(r[0]), "=r"(r[1]), "=r"(r[2]), "=r"(r[3]) : "r"(a));
}
__device__ __forceinline__ void mma16816(float* d, const unsigned* a, const unsigned* b) {
    asm volatile("mma.sync.aligned.m16n8k16.row.col.f32.f16.f16.f32 "
                 "{%0,%1,%2,%3}, {%4,%5,%6,%7}, {%8,%9}, {%0,%1,%2,%3};"
                 : "+f"(d[0]), "+f"(d[1]), "+f"(d[2]), "+f"(d[3])
                 : "r"(a[0]), "r"(a[1]), "r"(a[2]), "r"(a[3]),
                   "r"(b[0]), "r"(b[1]));
}
__device__ __forceinline__ void split_f16(float v, __half& h, __half& l) {
    h = __float2half_rn(v);
    l = __float2half_rn(v - __half2float(h));
}

// ---- cp.async (LDGSTS) staging ----
__device__ __forceinline__ void cp_async16(uint32_t s, const void* g) {
    asm volatile("cp.async.cg.shared.global [%0], [%1], 16;" :: "r"(s), "l"(g));
}
#define CP_COMMIT()  asm volatile("cp.async.commit_group;")
#define CP_WAIT1()   asm volatile("cp.async.wait_group 1;")
#define CP_WAIT0()   asm volatile("cp.async.wait_group 0;")

// stage rows x (COLS8*8) f16 tile gmem->smem (sync loads)
template<int COLS8>
__device__ __forceinline__ void stage(__half* s, int pitch,
                                      const __half* __restrict__ g,
                                      size_t gstride, int rows) {
    int tot = rows * COLS8;
    for (int i = threadIdx.x; i < tot; i += blockDim.x) {
        int r = i / COLS8, c = (i % COLS8) * 8;
        *(uint4*)(s + r*pitch + c) = *(const uint4*)(g + (size_t)r*gstride + c);
    }
}
// async variant
template<int COLS8>
__device__ __forceinline__ void stage_async(__half* s, int pitch,
                                            const __half* __restrict__ g,
                                            size_t gstride, int rows) {
    int tot = rows * COLS8;
    for (int i = threadIdx.x; i < tot; i += blockDim.x) {
        int r = i / COLS8, c = (i % COLS8) * 8;
        cp_async16(sm_addr(s + r*pitch + c), g + (size_t)r*gstride + c);
    }
}

// 3-term split MMA (accuracy-critical; both operands split)
template<int MI>
__device__ __forceinline__ void warp_mma3(float (&acc)[MI][4][4],
        const __half* Ah, const __half* Al, int pa,
        const __half* Bh, const __half* Bl, int pb,
        int m_base, int n_base, int lane) {
    const int ar = lane & 15, ac = (lane >> 4) * 8;
#pragma unroll
    for (int ks = 0; ks < 4; ks++) {
        unsigned ah[MI][4], al[MI][4], bh[2][4], bl[2][4];
#pragma unroll
        for (int mi = 0; mi < MI; mi++) {
            int off = (m_base + mi*16 + ar)*pa + ks*16 + ac;
            ldsm_x4(ah[mi], sm_addr(Ah + off));
            ldsm_x4(al[mi], sm_addr(Al + off));
        }
#pragma unroll
        for (int njp = 0; njp < 2; njp++) {
            int off = (ks*16 + ar)*pb + n_base + njp*16 + ac;
            ldsm_x4t(bh[njp], sm_addr(Bh + off));
            ldsm_x4t(bl[njp], sm_addr(Bl + off));
        }
#pragma unroll
        for (int mi = 0; mi < MI; mi++)
#pragma unroll
            for (int j = 0; j < 4; j++) {
                const unsigned* ph = &bh[j>>1][(j&1)*2];
                const unsigned* pl = &bl[j>>1][(j&1)*2];
                mma16816(acc[mi][j], ah[mi], ph);
                mma16816(acc[mi][j], ah[mi], pl);
                mma16816(acc[mi][j], al[mi], ph);
            }
    }
}

// 2-term split MMA: acc += Ah*(Bh+Bl).
template<int MI>
__device__ __forceinline__ void warp_mma2(float (&acc)[MI][4][4],
        const __half* Ah, int pa,
        const __half* Bh, const __half* Bl, int pb,
        int m_base, int n_base, int lane) {
    const int ar = lane & 15, ac = (lane >> 4) * 8;
#pragma unroll
    for (int ks = 0; ks < 4; ks++) {
        unsigned ah[MI][4], bh[2][4], bl[2][4];
#pragma unroll
        for (int mi = 0; mi < MI; mi++) {
            int off = (m_base + mi*16 + ar)*pa + ks*16 + ac;
            ldsm_x4(ah[mi], sm_addr(Ah + off));
        }
#pragma unroll
        for (int njp = 0; njp < 2; njp++) {
            int off = (ks*16 + ar)*pb + n_base + njp*16 + ac;
            ldsm_x4t(bh[njp], sm_addr(Bh + off));
            ldsm_x4t(bl[njp], sm_addr(Bl + off));
        }
#pragma unroll
        for (int mi = 0; mi < MI; mi++)
#pragma unroll
            for (int j = 0; j < 4; j++) {
                const unsigned* ph = &bh[j>>1][(j&1)*2];
                const unsigned* pl = &bl[j>>1][(j&1)*2];
                mma16816(acc[mi][j], ah[mi], ph);
                mma16816(acc[mi][j], ah[mi], pl);
            }
    }
}

// 1-term MMA: acc += Ah*Bh (error ~2^-12/term; used on relu-branch GEMMs)
template<int MI>
__device__ __forceinline__ void warp_mma1(float (&acc)[MI][4][4],
        const __half* Ah, int pa,
        const __half* Bh, int pb,
        int m_base, int n_base, int lane) {
    const int ar = lane & 15, ac = (lane >> 4) * 8;
#pragma unroll
    for (int ks = 0; ks < 4; ks++) {
        unsigned ah[MI][4], bh[2][4];
#pragma unroll
        for (int mi = 0; mi < MI; mi++) {
            int off = (m_base + mi*16 + ar)*pa + ks*16 + ac;
            ldsm_x4(ah[mi], sm_addr(Ah + off));
        }
#pragma unroll
        for (int njp = 0; njp < 2; njp++) {
            int off = (ks*16 + ar)*pb + n_base + njp*16 + ac;
            ldsm_x4t(bh[njp], sm_addr(Bh + off));
        }
#pragma unroll
        for (int mi = 0; mi < MI; mi++)
#pragma unroll
            for (int j = 0; j < 4; j++)
                mma16816(acc[mi][j], ah[mi], &bh[j>>1][(j&1)*2]);
    }
}

// ======================= scratch globals ====================================
__device__ float  g_supports[N_*N_];
__device__ __half g_sup_h[N_*N_];
__device__ __half g_A_h[N_*N_];
__device__ __half g_x_hi[(size_t)BT_*N_*C_],  g_x_lo[(size_t)BT_*N_*C_];
__device__ __half g_xT_hi[(size_t)BT_*C_*N_], g_xT_lo[(size_t)BT_*C_*N_];
__device__ __half g_wp_hi[(size_t)1024*4096], g_wp_lo[(size_t)1024*4096];
__device__ float  g_weights[N_*C_*C_];
__device__ float  g_bias[N_*C_];
__device__ float  g_bias_part[8*N_*C_];
__device__ float  g_score[(size_t)BT_*N_*N_];
__device__ __half g_P_h[(size_t)BT_*N_*N_];
__device__ float  g_xg[(size_t)BT_*N_*C_];

// ======================= small kernels ======================================
__global__ void k_supports(const float* __restrict__ e1,
                           const float* __restrict__ e2) {
    int j = blockIdx.x * 16 + threadIdx.x;
    int i = blockIdx.y * 16 + threadIdx.y;
    float d = 0.f;
#pragma unroll
    for (int k = 0; k < D_; k++)
        d += e1[i*D_+k]*e2[j*D_+k] - e2[i*D_+k]*e1[j*D_+k];
    float v = fmaxf(tanhf(d), 0.f);
    if (i == j) v += 1.f;
    g_supports[i*N_ + j] = v;
    g_sup_h[i*N_ + j] = __float2half_rn(v);
}

__global__ void k_softmaxA(const float* __restrict__ A_sym) {
    int row = blockIdx.x, t = threadIdx.x;
    const float* r = A_sym + (size_t)row * N_;
    __shared__ float red[256];
    float vals[4]; float m = -3.4e38f;
#pragma unroll
    for (int q = 0; q < 4; q++) { vals[q] = r[t + q*256]; m = fmaxf(m, vals[q]); }
    red[t] = m; __syncthreads();
    for (int s = 128; s > 0; s >>= 1) { if (t < s) red[t] = fmaxf(red[t], red[t+s]); __syncthreads(); }
    m = red[0]; __syncthreads();
    float sum = 0.f;
#pragma unroll
    for (int q = 0; q < 4; q++) { vals[q] = expf(vals[q] - m); sum += vals[q]; }
    red[t] = sum; __syncthreads();
    for (int s = 128; s > 0; s >>= 1) { if (t < s) red[t] += red[t+s]; __syncthreads(); }
    float inv = 1.f / red[0];
#pragma unroll
    for (int q = 0; q < 4; q++)
        g_A_h[(size_t)row*N_ + t + q*256] = __float2half_rn(vals[q] * inv);
}

__global__ void k_cvt_x(const float* __restrict__ x) {
    int bt = blockIdx.y, n0 = blockIdx.x * 64;
    __shared__ float tbuf[64][65];
    int tid = threadIdx.x;
    for (int e = tid; e < 4096; e += 256) {
        int n = e >> 6, c = e & 63;
        float v = x[((size_t)bt*N_ + n0 + n)*C_ + c];
        tbuf[n][c] = v;
        __half h, l; split_f16(v, h, l);
        size_t idx = ((size_t)bt*N_ + n0 + n)*C_ + c;
        g_x_hi[idx] = h; g_x_lo[idx] = l;
    }
    __syncthreads();
    for (int e = tid; e < 4096; e += 256) {
        int c = e >> 6, n = e & 63;
        float v = tbuf[n][c];
        __half h, l; split_f16(v, h, l);
        size_t idx = ((size_t)bt*C_ + c)*N_ + n0 + n;
        g_xT_hi[idx] = h; g_xT_lo[idx] = l;
    }
}

__global__ void k_cvt_wp(const float* __restrict__ wp) {
    size_t i = ((size_t)blockIdx.x*256 + threadIdx.x)*4;
    float4 v = *(const float4*)(wp + i);
    __half h, l;
    split_f16(v.x, h, l); g_wp_hi[i+0] = h; g_wp_lo[i+0] = l;
    split_f16(v.y, h, l); g_wp_hi[i+1] = h; g_wp_lo[i+1] = l;
    split_f16(v.z, h, l); g_wp_hi[i+2] = h; g_wp_lo[i+2] = l;
    split_f16(v.w, h, l); g_wp_hi[i+3] = h; g_wp_lo[i+3] = l;
}

// ======================= weights GEMM (2-MMA, double-buffered) ==============
#define W_AH 0
#define W_BH 9216
#define W_BL 17920
#define W_STG 26624
#define SMW_BYTES (2 * W_STG * 2)   // 106496

__global__ void __launch_bounds__(256) k_weights_mma() {
    extern __shared__ __half sm[];
    const int n0 = blockIdx.y * 128, io0 = blockIdx.x * 128;
    const int wid = threadIdx.x >> 5, lane = threadIdx.x & 31;
    const int m_base = (wid >> 2) * 64, n_base = (wid & 3) * 32;

    auto issue = [&](int ch) {
        __half* s = sm + (ch & 1) * W_STG;
        int ko = ch * 64;
        stage_async<8> (s+W_AH,  72, g_sup_h + (size_t)n0*N_ + ko, N_, 128);
        stage_async<16>(s+W_BH, 136, g_wp_hi + (size_t)ko*4096 + io0, 4096, 64);
        stage_async<16>(s+W_BL, 136, g_wp_lo + (size_t)ko*4096 + io0, 4096, 64);
        CP_COMMIT();
    };

    float acc[4][4][4] = {};
    issue(0);
    for (int ch = 0; ch < 16; ch++) {
        if (ch < 15) { issue(ch + 1); CP_WAIT1(); } else { CP_WAIT0(); }
        __syncthreads();
        __half* s = sm + (ch & 1) * W_STG;
        warp_mma2<4>(acc, s+W_AH, 72, s+W_BH, s+W_BL, 136,
                     m_base, n_base, lane);
        __syncthreads();
    }
#pragma unroll
    for (int mi = 0; mi < 4; mi++)
#pragma unroll
        for (int j = 0; j < 4; j++) {
            int r = n0 + m_base + mi*16 + (lane >> 2);
            int c = io0 + n_base + j*8 + (lane & 3)*2;
            g_weights[(size_t)r*4096 + c]       = acc[mi][j][0];
            g_weights[(size_t)r*4096 + c + 1]   = acc[mi][j][1];
            g_weights[(size_t)(r+8)*4096 + c]   = acc[mi][j][2];
            g_weights[(size_t)(r+8)*4096 + c+1] = acc[mi][j][3];
        }
}

// ======================= score GEMM (3-MMA, single K-chunk) =================
#define SC_AH 0
#define SC_AL 9216
#define SC_BH 18432
#define SC_BL 27136
#define SMSC_BYTES (35840 * 2)   // 71680

__global__ void __launch_bounds__(256) k_score_mma() {
    extern __shared__ __half sm[];
    const int bt = blockIdx.z, n0 = blockIdx.y * 128, m0 = blockIdx.x * 128;
    const int wid = threadIdx.x >> 5, lane = threadIdx.x & 31;
    const int m_base = (wid >> 2) * 64, n_base = (wid & 3) * 32;
    float acc[4][4][4] = {};
    stage<8> (sm+SC_AH,  72, g_x_hi + ((size_t)bt*N_ + n0)*C_, C_, 128);
    stage<8> (sm+SC_AL,  72, g_x_lo + ((size_t)bt*N_ + n0)*C_, C_, 128);
    stage<16>(sm+SC_BH, 136, g_xT_hi + (size_t)bt*C_*N_ + m0, N_, 64);
    stage<16>(sm+SC_BL, 136, g_xT_lo + (size_t)bt*C_*N_ + m0, N_, 64);
    __syncthreads();
    warp_mma3<4>(acc, sm+SC_AH, sm+SC_AL, 72, sm+SC_BH, sm+SC_BL, 136,
                 m_base, n_base, lane);
    float* S = g_score + (size_t)bt*N_*N_;
#pragma unroll
    for (int mi = 0; mi < 4; mi++)
#pragma unroll
        for (int j = 0; j < 4; j++) {
            int r = n0 + m_base + mi*16 + (lane >> 2);
            int c = m0 + n_base + j*8 + (lane & 3)*2;
            S[(size_t)r*N_ + c]       = acc[mi][j][0];
            S[(size_t)r*N_ + c + 1]   = acc[mi][j][1];
            S[(size_t)(r+8)*N_ + c]   = acc[mi][j][2];
            S[(size_t)(r+8)*N_ + c+1] = acc[mi][j][3];
        }
}

// ======================= softmax over T, float4-vectorized ==================
// each thread handles 4 consecutive elements of one (b, r) column set
__global__ void k_softmax_t() {
    size_t idx = (size_t)blockIdx.x * blockDim.x + threadIdx.x;  // B*N*N/4
    int b = (int)(idx >> 18);                 // N*N/4 = 2^18
    size_t r4 = (idx & ((1u << 18) - 1)) * 4;
    size_t base = (size_t)b * T_ * N_ * N_ + r4;
    float4 v[T_];
    float4 m = make_float4(-3.4e38f, -3.4e38f, -3.4e38f, -3.4e38f);
#pragma unroll
    for (int t = 0; t < T_; t++) {
        v[t] = *(const float4*)(g_score + base + (size_t)t * N_ * N_);
        m.x = fmaxf(m.x, v[t].x); m.y = fmaxf(m.y, v[t].y);
        m.z = fmaxf(m.z, v[t].z); m.w = fmaxf(m.w, v[t].w);
    }
    float4 sum = make_float4(0.f, 0.f, 0.f, 0.f);
#pragma unroll
    for (int t = 0; t < T_; t++) {
        v[t].x = __expf(v[t].x - m.x); sum.x += v[t].x;
        v[t].y = __expf(v[t].y - m.y); sum.y += v[t].y;
        v[t].z = __expf(v[t].z - m.z); sum.z += v[t].z;
        v[t].w = __expf(v[t].w - m.w); sum.w += v[t].w;
    }
    float4 inv = make_float4(1.f/sum.x, 1.f/sum.y, 1.f/sum.z, 1.f/sum.w);
#pragma unroll
    for (int t = 0; t < T_; t++) {
        __half2 p01 = __floats2half2_rn(v[t].x * inv.x, v[t].y * inv.y);
        __half2 p23 = __floats2half2_rn(v[t].z * inv.z, v[t].w * inv.w);
        uint2 pk;
        pk.x = *reinterpret_cast<unsigned*>(&p01);
        pk.y = *reinterpret_cast<unsigned*>(&p23);
        *(uint2*)(g_P_h + base + (size_t)t * N_ * N_) = pk;
    }
}

// ======================= sa: out += beta*relu(P @ X), 1-MMA =================
#define S_PH 0
#define S_XH 9216
#define S_STG 13824
#define SMS_BYTES (2 * S_STG * 2)   // 55296

__global__ void __launch_bounds__(256) k_sa_mma(const float* __restrict__ beta,
                                                float* __restrict__ out) {
    extern __shared__ __half sm[];
    const int bt = blockIdx.y, r0 = blockIdx.x * 128;
    const int wid = threadIdx.x >> 5, lane = threadIdx.x & 31;
    const int m_base = (wid >> 1) * 32, n_base = (wid & 1) * 32;

    auto issue = [&](int ch) {
        __half* s = sm + (ch & 1) * S_STG;
        int ko = ch * 64;
        stage_async<8>(s+S_PH, 72, g_P_h + ((size_t)bt*N_ + r0)*N_ + ko, N_, 128);
        stage_async<8>(s+S_XH, 72, g_x_hi + ((size_t)bt*N_ + ko)*C_, C_, 64);
        CP_COMMIT();
    };

    float acc[2][4][4] = {};
    issue(0);
    for (int ch = 0; ch < 16; ch++) {
        if (ch < 15) { issue(ch + 1); CP_WAIT1(); } else { CP_WAIT0(); }
        __syncthreads();
        __half* s = sm + (ch & 1) * S_STG;
        warp_mma1<2>(acc, s+S_PH, 72, s+S_XH, 72, m_base, n_base, lane);
        __syncthreads();
    }
    const float be = beta[0];
#pragma unroll
    for (int mi = 0; mi < 2; mi++)
#pragma unroll
        for (int j = 0; j < 4; j++) {
            int r = r0 + m_base + mi*16 + (lane >> 2);
            int c = n_base + j*8 + (lane & 3)*2;
            size_t i0 = ((size_t)bt*N_ + r)*C_ + c;
            size_t i8 = ((size_t)bt*N_ + r + 8)*C_ + c;
            out[i0]   += be * fmaxf(acc[mi][j][0], 0.f);
            out[i0+1] += be * fmaxf(acc[mi][j][1], 0.f);
            out[i8]   += be * fmaxf(acc[mi][j][2], 0.f);
            out[i8+1] += be * fmaxf(acc[mi][j][3], 0.f);
        }
}

// ======================= dual GEMM: 2 bt per block, 1-MMA ====================
#define D_A1H 0
#define D_A2H 9216
#define D_B0H 18432
#define D_B1H 23040
#define D_STG 27648
#define SMD_BYTES (2 * D_STG * 2)   // 110592

__global__ void __launch_bounds__(256) k_dual_mma(const float* __restrict__ gamma,
                                                  float* __restrict__ out) {
    extern __shared__ __half sm[];
    const int bt0 = blockIdx.y * 2, r0 = blockIdx.x * 128;
    const int wid = threadIdx.x >> 5, lane = threadIdx.x & 31;
    const int m_base = (wid >> 1) * 32, n_base = (wid & 1) * 32;

    auto issue = [&](int ch) {
        __half* s = sm + (ch & 1) * D_STG;
        int ko = ch * 64;
        stage_async<8>(s+D_A1H, 72, g_A_h   + (size_t)r0*N_ + ko, N_, 128);
        stage_async<8>(s+D_A2H, 72, g_sup_h + (size_t)r0*N_ + ko, N_, 128);
        stage_async<8>(s+D_B0H, 72, g_x_hi + ((size_t)bt0*N_ + ko)*C_, C_, 64);
        stage_async<8>(s+D_B1H, 72, g_x_hi + ((size_t)(bt0+1)*N_ + ko)*C_, C_, 64);
        CP_COMMIT();
    };

    float acc1[2][2][4][4] = {}, acc2[2][2][4][4] = {};
    issue(0);
    for (int ch = 0; ch < 16; ch++) {
        if (ch < 15) { issue(ch + 1); CP_WAIT1(); } else { CP_WAIT0(); }
        __syncthreads();
        __half* s = sm + (ch & 1) * D_STG;
        warp_mma1<2>(acc1[0], s+D_A1H, 72, s+D_B0H, 72, m_base, n_base, lane);
        warp_mma1<2>(acc2[0], s+D_A2H, 72, s+D_B0H, 72, m_base, n_base, lane);
        warp_mma1<2>(acc1[1], s+D_A1H, 72, s+D_B1H, 72, m_base, n_base, lane);
        warp_mma1<2>(acc2[1], s+D_A2H, 72, s+D_B1H, 72, m_base, n_base, lane);
        __syncthreads();
    }
    const float g = gamma[0];
#pragma unroll
    for (int q = 0; q < 2; q++) {
        int bt = bt0 + q;
#pragma unroll
        for (int mi = 0; mi < 2; mi++)
#pragma unroll
            for (int j = 0; j < 4; j++) {
                int r = r0 + m_base + mi*16 + (lane >> 2);
                int c = n_base + j*8 + (lane & 3)*2;
                size_t i0 = ((size_t)bt*N_ + r)*C_ + c;
                size_t i8 = ((size_t)bt*N_ + r + 8)*C_ + c;
                out[i0]   = g * fmaxf(acc1[q][mi][j][0], 0.f);
                out[i0+1] = g * fmaxf(acc1[q][mi][j][1], 0.f);
                out[i8]   = g * fmaxf(acc1[q][mi][j][2], 0.f);
                out[i8+1] = g * fmaxf(acc1[q][mi][j][3], 0.f);
                g_xg[i0]   = acc2[q][mi][j][0];
                g_xg[i0+1] = acc2[q][mi][j][1];
                g_xg[i8]   = acc2[q][mi][j][2];
                g_xg[i8+1] = acc2[q][mi][j][3];
            }
    }
}

// ======================= bias (fp32, split-K) ===============================
__global__ void k_bias_part(const float* __restrict__ bp) {
    __shared__ float As[16][68];
    __shared__ float Bs[16][68];
    int tid = threadIdx.x, tx = tid & 15, ty = tid >> 4;
    int m0 = blockIdx.x * 64, kb = blockIdx.y * 128;
    float acc[4][4] = {};
    for (int k0 = kb; k0 < kb + 128; k0 += 16) {
#pragma unroll
        for (int e = tid; e < 1024; e += 256) {
            int mm = e >> 4, kk = e & 15;
            As[kk][mm] = g_supports[(size_t)(m0+mm)*N_ + k0 + kk];
        }
#pragma unroll
        for (int e = tid; e < 1024; e += 256) {
            int kk = e >> 6, nn = e & 63;
            Bs[kk][nn] = bp[(size_t)(k0+kk)*C_ + nn];
        }
        __syncthreads();
#pragma unroll
        for (int k = 0; k < 16; k++) {
            float4 ra = *(const float4*)&As[k][ty<<2];
            float4 rb = *(const float4*)&Bs[k][tx<<2];
            float a[4] = {ra.x, ra.y, ra.z, ra.w};
            float b[4] = {rb.x, rb.y, rb.z, rb.w};
#pragma unroll
            for (int i = 0; i < 4; i++)
#pragma unroll
                for (int j = 0; j < 4; j++) acc[i][j] += a[i]*b[j];
        }
        __syncthreads();
    }
    float* dst = g_bias_part + (size_t)blockIdx.y * N_ * C_;
#pragma unroll
    for (int i = 0; i < 4; i++)
#pragma unroll
        for (int j = 0; j < 4; j++)
            dst[(size_t)(m0+(ty<<2)+i)*C_ + (tx<<2) + j] = acc[i][j];
}
__global__ void k_bias_red() {
    int i = blockIdx.x * 256 + threadIdx.x;
    float s = 0.f;
#pragma unroll
    for (int c = 0; c < 8; c++) s += g_bias_part[(size_t)c*N_*C_ + i];
    g_bias[i] = s;
}

// ---------------- gconv: out += alpha*relu(xg[:,n,:] @ W[n] + bias[n]) ------
__global__ void k_gconv(const float* __restrict__ alpha,
                        float* __restrict__ out) {
    int n = blockIdx.x, tid = threadIdx.x;
    __shared__ float Ws[64*64];
    __shared__ float Xs[96][64];
    __shared__ float bs[64];
#pragma unroll
    for (int e = tid; e < 4096; e += 256) Ws[e] = g_weights[(size_t)n*4096 + e];
    if (tid < 64) bs[tid] = g_bias[(size_t)n*64 + tid];
#pragma unroll
    for (int e = tid; e < 96*64; e += 256) {
        int r = e >> 6, c = e & 63;
        Xs[r][c] = g_xg[((size_t)r*N_ + n)*C_ + c];
    }
    __syncthreads();
    float al = alpha[0];
    int o = tid & 63, rg = tid >> 6;
    for (int r = rg; r < 96; r += 4) {
        float acc = bs[o];
#pragma unroll
        for (int i = 0; i < 64; i++) acc = fmaf(Xs[r][i], Ws[i*64 + o], acc);
        size_t idx = ((size_t)r*N_ + n)*C_ + o;
        out[idx] += al * fmaxf(acc, 0.f);
    }
}

// ======================= launch =============================================
extern "C" void kernel_launch(void* const* d_in, const int* in_sizes, int n_in,
                              void* d_out, int out_size) {
    (void)in_sizes; (void)n_in; (void)out_size;
    const float* x     = (const float*)d_in[0];
    const float* e1    = (const float*)d_in[1];
    const float* e2    = (const float*)d_in[2];
    const float* A_sym = (const float*)d_in[3];
    const float* wp    = (const float*)d_in[4];
    const float* bp    = (const float*)d_in[5];
    const float* alpha = (const float*)d_in[6];
    const float* beta  = (const float*)d_in[7];
    const float* gamma = (const float*)d_in[8];
    float* out = (float*)d_out;

    static cudaStream_t s2 = nullptr;
    static cudaEvent_t evFork = nullptr, evSup = nullptr, evW = nullptr;
    if (s2 == nullptr) {
        cudaStreamCreateWithFlags(&s2, cudaStreamNonBlocking);
        cudaEventCreateWithFlags(&evFork, cudaEventDisableTiming);
        cudaEventCreateWithFlags(&evSup,  cudaEventDisableTiming);
        cudaEventCreateWithFlags(&evW,    cudaEventDisableTiming);
        cudaFuncSetAttribute(k_weights_mma, cudaFuncAttributeMaxDynamicSharedMemorySize, SMW_BYTES);
        cudaFuncSetAttribute(k_score_mma,   cudaFuncAttributeMaxDynamicSharedMemorySize, SMSC_BYTES);
        cudaFuncSetAttribute(k_sa_mma,      cudaFuncAttributeMaxDynamicSharedMemorySize, SMS_BYTES);
        cudaFuncSetAttribute(k_dual_mma,    cudaFuncAttributeMaxDynamicSharedMemorySize, SMD_BYTES);
    }

    // ---- fork: chain A (cvt_wp -> weights -> bias) on s2 ----
    cudaEventRecord(evFork, 0);
    cudaStreamWaitEvent(s2, evFork, 0);
    k_cvt_wp<<<(1024*4096)/(256*4), 256, 0, s2>>>(wp);

    k_supports<<<dim3(N_/16, N_/16), dim3(16,16)>>>(e1, e2);
    cudaEventRecord(evSup, 0);
    cudaStreamWaitEvent(s2, evSup, 0);

    k_weights_mma<<<dim3(32, 8), 256, SMW_BYTES, s2>>>();
    k_bias_part  <<<dim3(N_/64, 8), 256, 0, s2>>>(bp);
    k_bias_red   <<<(N_*C_)/256, 256, 0, s2>>>();
    cudaEventRecord(evW, s2);

    // main: chain B (critical path)
    k_softmaxA <<<N_, 256>>>(A_sym);
    k_cvt_x    <<<dim3(N_/64, BT_), 256>>>(x);
    k_score_mma<<<dim3(8, 8, BT_), 256, SMSC_BYTES>>>();
    k_softmax_t<<<(B_*N_*N_)/(256*4), 256>>>();
    k_dual_mma <<<dim3(8, BT_/2), 256, SMD_BYTES>>>(gamma, out);
    k_sa_mma   <<<dim3(8, BT_), 256, SMS_BYTES>>>(beta, out);

    // ---- join: gconv needs weights+bias (chain A) and xg (dual) ----
    cudaStreamWaitEvent(0, evW, 0);
    k_gconv<<<N_, 256>>>(alpha, out);
}

// round 16
// speedup vs baseline: 2.0135x; 1.0018x over previous
#include <cuda_runtime.h>
#include <cuda_fp16.h>
#include <math.h>
#include <stdint.h>

#define B_  8
#define T_  12
#define N_  1024
#define C_  64
#define D_  10
#define BT_ (B_*T_)   // 96

// ======================= mma.sync / ldmatrix helpers ========================
__device__ __forceinline__ uint32_t sm_addr(const void* p) {
    return (uint32_t)__cvta_generic_to_shared(p);
}
__device__ __forceinline__ void ldsm_x4(unsigned* r, uint32_t a) {
    asm volatile("ldmatrix.sync.aligned.m8n8.x4.shared.b16 {%0,%1,%2,%3}, [%4];"
                 : "=r"(r[0]), "=r"(r[1]), "=r"(r[2]), "=r"(r[3]) : "r"(a));
}
__device__ __forceinline__ void ldsm_x4t(unsigned* r, uint32_t a) {
    asm volatile("ldmatrix.sync.aligned.m8n8.x4.trans.shared.b16 {%0,%1,%2,%3}, [%4];"
                 : "=r"(r[0]), "=r"(r[1]), "=r"(r[2]), "=r"(r[3]) : "r"(a));
}
__device__ __forceinline__ void mma16816(float* d, const unsigned* a, const unsigned* b) {
    asm volatile("mma.sync.aligned.m16n8k16.row.col.f32.f16.f16.f32 "
                 "{%0,%1,%2,%3}, {%4,%5,%6,%7}, {%8,%9}, {%0,%1,%2,%3};"
                 : "+f"(d[0]), "+f"(d[1]), "+f"(d[2]), "+f"(d[3])
                 : "r"(a[0]), "r"(a[1]), "r"(a[2]), "r"(a[3]),
                   "r"(b[0]), "r"(b[1]));
}
__device__ __forceinline__ void split_f16(float v, __half& h, __half& l) {
    h = __float2half_rn(v);
    l = __float2half_rn(v - __half2float(h));
}

// ---- cp.async (LDGSTS) staging ----
__device__ __forceinline__ void cp_async16(uint32_t s, const void* g) {
    asm volatile("cp.async.cg.shared.global [%0], [%1], 16;" :: "r"(s), "l"(g));
}
#define CP_COMMIT()  asm volatile("cp.async.commit_group;")
#define CP_WAIT1()   asm volatile("cp.async.wait_group 1;")
#define CP_WAIT0()   asm volatile("cp.async.wait_group 0;")

// stage rows x (COLS8*8) f16 tile gmem->smem (sync loads)
template<int COLS8>
__device__ __forceinline__ void stage(__half* s, int pitch,
                                      const __half* __restrict__ g,
                                      size_t gstride, int rows) {
    int tot = rows * COLS8;
    for (int i = threadIdx.x; i < tot; i += blockDim.x) {
        int r = i / COLS8, c = (i % COLS8) * 8;
        *(uint4*)(s + r*pitch + c) = *(const uint4*)(g + (size_t)r*gstride + c);
    }
}
// async variant
template<int COLS8>
__device__ __forceinline__ void stage_async(__half* s, int pitch,
                                            const __half* __restrict__ g,
                                            size_t gstride, int rows) {
    int tot = rows * COLS8;
    for (int i = threadIdx.x; i < tot; i += blockDim.x) {
        int r = i / COLS8, c = (i % COLS8) * 8;
        cp_async16(sm_addr(s + r*pitch + c), g + (size_t)r*gstride + c);
    }
}

// 3-term split MMA (accuracy-critical; both operands split)
template<int MI>
__device__ __forceinline__ void warp_mma3(float (&acc)[MI][4][4],
        const __half* Ah, const __half* Al, int pa,
        const __half* Bh, const __half* Bl, int pb,
        int m_base, int n_base, int lane) {
    const int ar = lane & 15, ac = (lane >> 4) * 8;
#pragma unroll
    for (int ks = 0; ks < 4; ks++) {
        unsigned ah[MI][4], al[MI][4], bh[2][4], bl[2][4];
#pragma unroll
        for (int mi = 0; mi < MI; mi++) {
            int off = (m_base + mi*16 + ar)*pa + ks*16 + ac;
            ldsm_x4(ah[mi], sm_addr(Ah + off));
            ldsm_x4(al[mi], sm_addr(Al + off));
        }
#pragma unroll
        for (int njp = 0; njp < 2; njp++) {
            int off = (ks*16 + ar)*pb + n_base + njp*16 + ac;
            ldsm_x4t(bh[njp], sm_addr(Bh + off));
            ldsm_x4t(bl[njp], sm_addr(Bl + off));
        }
#pragma unroll
        for (int mi = 0; mi < MI; mi++)
#pragma unroll
            for (int j = 0; j < 4; j++) {
                const unsigned* ph = &bh[j>>1][(j&1)*2];
                const unsigned* pl = &bl[j>>1][(j&1)*2];
                mma16816(acc[mi][j], ah[mi], ph);
                mma16816(acc[mi][j], ah[mi], pl);
                mma16816(acc[mi][j], al[mi], ph);
            }
    }
}

// 2-term split MMA: acc += Ah*(Bh+Bl).
template<int MI>
__device__ __forceinline__ void warp_mma2(float (&acc)[MI][4][4],
        const __half* Ah, int pa,
        const __half* Bh, const __half* Bl, int pb,
        int m_base, int n_base, int lane) {
    const int ar = lane & 15, ac = (lane >> 4) * 8;
#pragma unroll
    for (int ks = 0; ks < 4; ks++) {
        unsigned ah[MI][4], bh[2][4], bl[2][4];
#pragma unroll
        for (int mi = 0; mi < MI; mi++) {
            int off = (m_base + mi*16 + ar)*pa + ks*16 + ac;
            ldsm_x4(ah[mi], sm_addr(Ah + off));
        }
#pragma unroll
        for (int njp = 0; njp < 2; njp++) {
            int off = (ks*16 + ar)*pb + n_base + njp*16 + ac;
            ldsm_x4t(bh[njp], sm_addr(Bh + off));
            ldsm_x4t(bl[njp], sm_addr(Bl + off));
        }
#pragma unroll
        for (int mi = 0; mi < MI; mi++)
#pragma unroll
            for (int j = 0; j < 4; j++) {
                const unsigned* ph = &bh[j>>1][(j&1)*2];
                const unsigned* pl = &bl[j>>1][(j&1)*2];
                mma16816(acc[mi][j], ah[mi], ph);
                mma16816(acc[mi][j], ah[mi], pl);
            }
    }
}

// 1-term MMA: acc += Ah*Bh
template<int MI>
__device__ __forceinline__ void warp_mma1(float (&acc)[MI][4][4],
        const __half* Ah, int pa,
        const __half* Bh, int pb,
        int m_base, int n_base, int lane) {
    const int ar = lane & 15, ac = (lane >> 4) * 8;
#pragma unroll
    for (int ks = 0; ks < 4; ks++) {
        unsigned ah[MI][4], bh[2][4];
#pragma unroll
        for (int mi = 0; mi < MI; mi++) {
            int off = (m_base + mi*16 + ar)*pa + ks*16 + ac;
            ldsm_x4(ah[mi], sm_addr(Ah + off));
        }
#pragma unroll
        for (int njp = 0; njp < 2; njp++) {
            int off = (ks*16 + ar)*pb + n_base + njp*16 + ac;
            ldsm_x4t(bh[njp], sm_addr(Bh + off));
        }
#pragma unroll
        for (int mi = 0; mi < MI; mi++)
#pragma unroll
            for (int j = 0; j < 4; j++)
                mma16816(acc[mi][j], ah[mi], &bh[j>>1][(j&1)*2]);
    }
}

// ======================= scratch globals ====================================
__device__ float  g_supports[N_*N_];
__device__ __half g_sup_h[N_*N_];
__device__ __half g_A_h[N_*N_];
__device__ __half g_x_hi[(size_t)BT_*N_*C_],  g_x_lo[(size_t)BT_*N_*C_];
__device__ __half g_xT_hi[(size_t)BT_*C_*N_], g_xT_lo[(size_t)BT_*C_*N_];
__device__ __half g_wp_hi[(size_t)1024*4096], g_wp_lo[(size_t)1024*4096];
__device__ float  g_weights[N_*C_*C_];
__device__ float  g_bias[N_*C_];
__device__ float  g_bias_part[8*N_*C_];
__device__ float  g_score[(size_t)BT_*N_*N_];
__device__ __half g_P_h[(size_t)BT_*N_*N_];
__device__ float  g_xg[(size_t)BT_*N_*C_];

// ======================= small kernels ======================================
__global__ void k_supports(const float* __restrict__ e1,
                           const float* __restrict__ e2) {
    int j = blockIdx.x * 16 + threadIdx.x;
    int i = blockIdx.y * 16 + threadIdx.y;
    float d = 0.f;
#pragma unroll
    for (int k = 0; k < D_; k++)
        d += e1[i*D_+k]*e2[j*D_+k] - e2[i*D_+k]*e1[j*D_+k];
    float v = fmaxf(tanhf(d), 0.f);
    if (i == j) v += 1.f;
    g_supports[i*N_ + j] = v;
    g_sup_h[i*N_ + j] = __float2half_rn(v);
}

__global__ void k_softmaxA(const float* __restrict__ A_sym) {
    int row = blockIdx.x, t = threadIdx.x;
    const float* r = A_sym + (size_t)row * N_;
    __shared__ float red[256];
    float vals[4]; float m = -3.4e38f;
#pragma unroll
    for (int q = 0; q < 4; q++) { vals[q] = r[t + q*256]; m = fmaxf(m, vals[q]); }
    red[t] = m; __syncthreads();
    for (int s = 128; s > 0; s >>= 1) { if (t < s) red[t] = fmaxf(red[t], red[t+s]); __syncthreads(); }
    m = red[0]; __syncthreads();
    float sum = 0.f;
#pragma unroll
    for (int q = 0; q < 4; q++) { vals[q] = expf(vals[q] - m); sum += vals[q]; }
    red[t] = sum; __syncthreads();
    for (int s = 128; s > 0; s >>= 1) { if (t < s) red[t] += red[t+s]; __syncthreads(); }
    float inv = 1.f / red[0];
#pragma unroll
    for (int q = 0; q < 4; q++)
        g_A_h[(size_t)row*N_ + t + q*256] = __float2half_rn(vals[q] * inv);
}

__global__ void k_cvt_x(const float* __restrict__ x) {
    int bt = blockIdx.y, n0 = blockIdx.x * 64;
    __shared__ float tbuf[64][65];
    int tid = threadIdx.x;
    for (int e = tid; e < 4096; e += 256) {
        int n = e >> 6, c = e & 63;
        float v = x[((size_t)bt*N_ + n0 + n)*C_ + c];
        tbuf[n][c] = v;
        __half h, l; split_f16(v, h, l);
        size_t idx = ((size_t)bt*N_ + n0 + n)*C_ + c;
        g_x_hi[idx] = h; g_x_lo[idx] = l;
    }
    __syncthreads();
    for (int e = tid; e < 4096; e += 256) {
        int c = e >> 6, n = e & 63;
        float v = tbuf[n][c];
        __half h, l; split_f16(v, h, l);
        size_t idx = ((size_t)bt*C_ + c)*N_ + n0 + n;
        g_xT_hi[idx] = h; g_xT_lo[idx] = l;
    }
}

__global__ void k_cvt_wp(const float* __restrict__ wp) {
    size_t i = ((size_t)blockIdx.x*256 + threadIdx.x)*4;
    float4 v = *(const float4*)(wp + i);
    __half h, l;
    split_f16(v.x, h, l); g_wp_hi[i+0] = h; g_wp_lo[i+0] = l;
    split_f16(v.y, h, l); g_wp_hi[i+1] = h; g_wp_lo[i+1] = l;
    split_f16(v.z, h, l); g_wp_hi[i+2] = h; g_wp_lo[i+2] = l;
    split_f16(v.w, h, l); g_wp_hi[i+3] = h; g_wp_lo[i+3] = l;
}

// ======================= weights GEMM (2-MMA, double-buffered) ==============
#define W_AH 0
#define W_BH 9216
#define W_BL 17920
#define W_STG 26624
#define SMW_BYTES (2 * W_STG * 2)   // 106496

__global__ void __launch_bounds__(256) k_weights_mma() {
    extern __shared__ __half sm[];
    const int n0 = blockIdx.y * 128, io0 = blockIdx.x * 128;
    const int wid = threadIdx.x >> 5, lane = threadIdx.x & 31;
    const int m_base = (wid >> 2) * 64, n_base = (wid & 3) * 32;

    auto issue = [&](int ch) {
        __half* s = sm + (ch & 1) * W_STG;
        int ko = ch * 64;
        stage_async<8> (s+W_AH,  72, g_sup_h + (size_t)n0*N_ + ko, N_, 128);
        stage_async<16>(s+W_BH, 136, g_wp_hi + (size_t)ko*4096 + io0, 4096, 64);
        stage_async<16>(s+W_BL, 136, g_wp_lo + (size_t)ko*4096 + io0, 4096, 64);
        CP_COMMIT();
    };

    float acc[4][4][4] = {};
    issue(0);
    for (int ch = 0; ch < 16; ch++) {
        if (ch < 15) { issue(ch + 1); CP_WAIT1(); } else { CP_WAIT0(); }
        __syncthreads();
        __half* s = sm + (ch & 1) * W_STG;
        warp_mma2<4>(acc, s+W_AH, 72, s+W_BH, s+W_BL, 136,
                     m_base, n_base, lane);
        __syncthreads();
    }
#pragma unroll
    for (int mi = 0; mi < 4; mi++)
#pragma unroll
        for (int j = 0; j < 4; j++) {
            int r = n0 + m_base + mi*16 + (lane >> 2);
            int c = io0 + n_base + j*8 + (lane & 3)*2;
            g_weights[(size_t)r*4096 + c]       = acc[mi][j][0];
            g_weights[(size_t)r*4096 + c + 1]   = acc[mi][j][1];
            g_weights[(size_t)(r+8)*4096 + c]   = acc[mi][j][2];
            g_weights[(size_t)(r+8)*4096 + c+1] = acc[mi][j][3];
        }
}

// ======================= score GEMM (3-MMA, per-b) ==========================
#define SC_AH 0
#define SC_AL 9216
#define SC_BH 18432
#define SC_BL 27136
#define SMSC_BYTES (35840 * 2)   // 71680

__global__ void __launch_bounds__(256) k_score_mma(int bt0) {
    extern __shared__ __half sm[];
    const int bt = bt0 + blockIdx.z, n0 = blockIdx.y * 128, m0 = blockIdx.x * 128;
    const int wid = threadIdx.x >> 5, lane = threadIdx.x & 31;
    const int m_base = (wid >> 2) * 64, n_base = (wid & 3) * 32;
    float acc[4][4][4] = {};
    stage<8> (sm+SC_AH,  72, g_x_hi + ((size_t)bt*N_ + n0)*C_, C_, 128);
    stage<8> (sm+SC_AL,  72, g_x_lo + ((size_t)bt*N_ + n0)*C_, C_, 128);
    stage<16>(sm+SC_BH, 136, g_xT_hi + (size_t)bt*C_*N_ + m0, N_, 64);
    stage<16>(sm+SC_BL, 136, g_xT_lo + (size_t)bt*C_*N_ + m0, N_, 64);
    __syncthreads();
    warp_mma3<4>(acc, sm+SC_AH, sm+SC_AL, 72, sm+SC_BH, sm+SC_BL, 136,
                 m_base, n_base, lane);
    float* S = g_score + (size_t)bt*N_*N_;
#pragma unroll
    for (int mi = 0; mi < 4; mi++)
#pragma unroll
        for (int j = 0; j < 4; j++) {
            int r = n0 + m_base + mi*16 + (lane >> 2);
            int c = m0 + n_base + j*8 + (lane & 3)*2;
            S[(size_t)r*N_ + c]       = acc[mi][j][0];
            S[(size_t)r*N_ + c + 1]   = acc[mi][j][1];
            S[(size_t)(r+8)*N_ + c]   = acc[mi][j][2];
            S[(size_t)(r+8)*N_ + c+1] = acc[mi][j][3];
        }
}

// ======================= softmax over T, float4-vectorized, per-b ===========
__global__ void k_softmax_t(int b) {
    size_t idx = (size_t)blockIdx.x * blockDim.x + threadIdx.x;  // N*N/4
    size_t r4 = idx * 4;
    size_t base = (size_t)b * T_ * N_ * N_ + r4;
    float4 v[T_];
    float4 m = make_float4(-3.4e38f, -3.4e38f, -3.4e38f, -3.4e38f);
#pragma unroll
    for (int t = 0; t < T_; t++) {
        v[t] = *(const float4*)(g_score + base + (size_t)t * N_ * N_);
        m.x = fmaxf(m.x, v[t].x); m.y = fmaxf(m.y, v[t].y);
        m.z = fmaxf(m.z, v[t].z); m.w = fmaxf(m.w, v[t].w);
    }
    float4 sum = make_float4(0.f, 0.f, 0.f, 0.f);
#pragma unroll
    for (int t = 0; t < T_; t++) {
        v[t].x = __expf(v[t].x - m.x); sum.x += v[t].x;
        v[t].y = __expf(v[t].y - m.y); sum.y += v[t].y;
        v[t].z = __expf(v[t].z - m.z); sum.z += v[t].z;
        v[t].w = __expf(v[t].w - m.w); sum.w += v[t].w;
    }
    float4 inv = make_float4(1.f/sum.x, 1.f/sum.y, 1.f/sum.z, 1.f/sum.w);
#pragma unroll
    for (int t = 0; t < T_; t++) {
        __half2 p01 = __floats2half2_rn(v[t].x * inv.x, v[t].y * inv.y);
        __half2 p23 = __floats2half2_rn(v[t].z * inv.z, v[t].w * inv.w);
        uint2 pk;
        pk.x = *reinterpret_cast<unsigned*>(&p01);
        pk.y = *reinterpret_cast<unsigned*>(&p23);
        *(uint2*)(g_P_h + base + (size_t)t * N_ * N_) = pk;
    }
}

// ======================= sa: out += beta*relu(P @ X), 1-MMA, per-b ==========
#define S_PH 0
#define S_XH 9216
#define S_STG 13824
#define SMS_BYTES (2 * S_STG * 2)   // 55296

__global__ void __launch_bounds__(256) k_sa_mma(int b,
                                                const float* __restrict__ beta,
                                                float* __restrict__ out) {
    extern __shared__ __half sm[];
    const int bt = b * T_ + blockIdx.y, r0 = blockIdx.x * 128;
    const int wid = threadIdx.x >> 5, lane = threadIdx.x & 31;
    const int m_base = (wid >> 1) * 32, n_base = (wid & 1) * 32;

    auto issue = [&](int ch) {
        __half* s = sm + (ch & 1) * S_STG;
        int ko = ch * 64;
        stage_async<8>(s+S_PH, 72, g_P_h + ((size_t)bt*N_ + r0)*N_ + ko, N_, 128);
        stage_async<8>(s+S_XH, 72, g_x_hi + ((size_t)bt*N_ + ko)*C_, C_, 64);
        CP_COMMIT();
    };

    float acc[2][4][4] = {};
    issue(0);
    for (int ch = 0; ch < 16; ch++) {
        if (ch < 15) { issue(ch + 1); CP_WAIT1(); } else { CP_WAIT0(); }
        __syncthreads();
        __half* s = sm + (ch & 1) * S_STG;
        warp_mma1<2>(acc, s+S_PH, 72, s+S_XH, 72, m_base, n_base, lane);
        __syncthreads();
    }
    const float be = beta[0];
#pragma unroll
    for (int mi = 0; mi < 2; mi++)
#pragma unroll
        for (int j = 0; j < 4; j++) {
            int r = r0 + m_base + mi*16 + (lane >> 2);
            int c = n_base + j*8 + (lane & 3)*2;
            size_t i0 = ((size_t)bt*N_ + r)*C_ + c;
            size_t i8 = ((size_t)bt*N_ + r + 8)*C_ + c;
            out[i0]   += be * fmaxf(acc[mi][j][0], 0.f);
            out[i0+1] += be * fmaxf(acc[mi][j][1], 0.f);
            out[i8]   += be * fmaxf(acc[mi][j][2], 0.f);
            out[i8+1] += be * fmaxf(acc[mi][j][3], 0.f);
        }
}

// ======================= dual GEMM: 2 bt per block, 1-MMA ====================
#define D_A1H 0
#define D_A2H 9216
#define D_B0H 18432
#define D_B1H 23040
#define D_STG 27648
#define SMD_BYTES (2 * D_STG * 2)   // 110592

__global__ void __launch_bounds__(256) k_dual_mma(const float* __restrict__ gamma,
                                                  float* __restrict__ out) {
    extern __shared__ __half sm[];
    const int bt0 = blockIdx.y * 2, r0 = blockIdx.x * 128;
    const int wid = threadIdx.x >> 5, lane = threadIdx.x & 31;
    const int m_base = (wid >> 1) * 32, n_base = (wid & 1) * 32;

    auto issue = [&](int ch) {
        __half* s = sm + (ch & 1) * D_STG;
        int ko = ch * 64;
        stage_async<8>(s+D_A1H, 72, g_A_h   + (size_t)r0*N_ + ko, N_, 128);
        stage_async<8>(s+D_A2H, 72, g_sup_h + (size_t)r0*N_ + ko, N_, 128);
        stage_async<8>(s+D_B0H, 72, g_x_hi + ((size_t)bt0*N_ + ko)*C_, C_, 64);
        stage_async<8>(s+D_B1H, 72, g_x_hi + ((size_t)(bt0+1)*N_ + ko)*C_, C_, 64);
        CP_COMMIT();
    };

    float acc1[2][2][4][4] = {}, acc2[2][2][4][4] = {};
    issue(0);
    for (int ch = 0; ch < 16; ch++) {
        if (ch < 15) { issue(ch + 1); CP_WAIT1(); } else { CP_WAIT0(); }
        __syncthreads();
        __half* s = sm + (ch & 1) * D_STG;
        warp_mma1<2>(acc1[0], s+D_A1H, 72, s+D_B0H, 72, m_base, n_base, lane);
        warp_mma1<2>(acc2[0], s+D_A2H, 72, s+D_B0H, 72, m_base, n_base, lane);
        warp_mma1<2>(acc1[1], s+D_A1H, 72, s+D_B1H, 72, m_base, n_base, lane);
        warp_mma1<2>(acc2[1], s+D_A2H, 72, s+D_B1H, 72, m_base, n_base, lane);
        __syncthreads();
    }
    const float g = gamma[0];
#pragma unroll
    for (int q = 0; q < 2; q++) {
        int bt = bt0 + q;
#pragma unroll
        for (int mi = 0; mi < 2; mi++)
#pragma unroll
            for (int j = 0; j < 4; j++) {
                int r = r0 + m_base + mi*16 + (lane >> 2);
                int c = n_base + j*8 + (lane & 3)*2;
                size_t i0 = ((size_t)bt*N_ + r)*C_ + c;
                size_t i8 = ((size_t)bt*N_ + r + 8)*C_ + c;
                out[i0]   = g * fmaxf(acc1[q][mi][j][0], 0.f);
                out[i0+1] = g * fmaxf(acc1[q][mi][j][1], 0.f);
                out[i8]   = g * fmaxf(acc1[q][mi][j][2], 0.f);
                out[i8+1] = g * fmaxf(acc1[q][mi][j][3], 0.f);
                g_xg[i0]   = acc2[q][mi][j][0];
                g_xg[i0+1] = acc2[q][mi][j][1];
                g_xg[i8]   = acc2[q][mi][j][2];
                g_xg[i8+1] = acc2[q][mi][j][3];
            }
    }
}

// ======================= bias (fp32, split-K) ===============================
__global__ void k_bias_part(const float* __restrict__ bp) {
    __shared__ float As[16][68];
    __shared__ float Bs[16][68];
    int tid = threadIdx.x, tx = tid & 15, ty = tid >> 4;
    int m0 = blockIdx.x * 64, kb = blockIdx.y * 128;
    float acc[4][4] = {};
    for (int k0 = kb; k0 < kb + 128; k0 += 16) {
#pragma unroll
        for (int e = tid; e < 1024; e += 256) {
            int mm = e >> 4, kk = e & 15;
            As[kk][mm] = g_supports[(size_t)(m0+mm)*N_ + k0 + kk];
        }
#pragma unroll
        for (int e = tid; e < 1024; e += 256) {
            int kk = e >> 6, nn = e & 63;
            Bs[kk][nn] = bp[(size_t)(k0+kk)*C_ + nn];
        }
        __syncthreads();
#pragma unroll
        for (int k = 0; k < 16; k++) {
            float4 ra = *(const float4*)&As[k][ty<<2];
            float4 rb = *(const float4*)&Bs[k][tx<<2];
            float a[4] = {ra.x, ra.y, ra.z, ra.w};
            float b[4] = {rb.x, rb.y, rb.z, rb.w};
#pragma unroll
            for (int i = 0; i < 4; i++)
#pragma unroll
                for (int j = 0; j < 4; j++) acc[i][j] += a[i]*b[j];
        }
        __syncthreads();
    }
    float* dst = g_bias_part + (size_t)blockIdx.y * N_ * C_;
#pragma unroll
    for (int i = 0; i < 4; i++)
#pragma unroll
        for (int j = 0; j < 4; j++)
            dst[(size_t)(m0+(ty<<2)+i)*C_ + (tx<<2) + j] = acc[i][j];
}
__global__ void k_bias_red() {
    int i = blockIdx.x * 256 + threadIdx.x;
    float s = 0.f;
#pragma unroll
    for (int c = 0; c < 8; c++) s += g_bias_part[(size_t)c*N_*C_ + i];
    g_bias[i] = s;
}

// ---------------- gconv: out += alpha*relu(xg[:,n,:] @ W[n] + bias[n]) ------
__global__ void k_gconv(const float* __restrict__ alpha,
                        float* __restrict__ out) {
    int n = blockIdx.x, tid = threadIdx.x;
    __shared__ float Ws[64*64];
    __shared__ float Xs[96][64];
    __shared__ float bs[64];
#pragma unroll
    for (int e = tid; e < 4096; e += 256) Ws[e] = g_weights[(size_t)n*4096 + e];
    if (tid < 64) bs[tid] = g_bias[(size_t)n*64 + tid];
#pragma unroll
    for (int e = tid; e < 96*64; e += 256) {
        int r = e >> 6, c = e & 63;
        Xs[r][c] = g_xg[((size_t)r*N_ + n)*C_ + c];
    }
    __syncthreads();
    float al = alpha[0];
    int o = tid & 63, rg = tid >> 6;
    for (int r = rg; r < 96; r += 4) {
        float acc = bs[o];
#pragma unroll
        for (int i = 0; i < 64; i++) acc = fmaf(Xs[r][i], Ws[i*64 + o], acc);
        size_t idx = ((size_t)r*N_ + n)*C_ + o;
        out[idx] += al * fmaxf(acc, 0.f);
    }
}

// ======================= launch =============================================
extern "C" void kernel_launch(void* const* d_in, const int* in_sizes, int n_in,
                              void* d_out, int out_size) {
    (void)in_sizes; (void)n_in; (void)out_size;
    const float* x     = (const float*)d_in[0];
    const float* e1    = (const float*)d_in[1];
    const float* e2    = (const float*)d_in[2];
    const float* A_sym = (const float*)d_in[3];
    const float* wp    = (const float*)d_in[4];
    const float* bp    = (const float*)d_in[5];
    const float* alpha = (const float*)d_in[6];
    const float* beta  = (const float*)d_in[7];
    const float* gamma = (const float*)d_in[8];
    float* out = (float*)d_out;

    static cudaStream_t s2 = nullptr, s3 = nullptr;
    static cudaEvent_t evFork, evSup, evCvtX, evDual, evW, evSA;
    static cudaEvent_t evSM[B_];
    if (s2 == nullptr) {
        cudaStreamCreateWithFlags(&s2, cudaStreamNonBlocking);
        cudaStreamCreateWithFlags(&s3, cudaStreamNonBlocking);
        cudaEventCreateWithFlags(&evFork, cudaEventDisableTiming);
        cudaEventCreateWithFlags(&evSup,  cudaEventDisableTiming);
        cudaEventCreateWithFlags(&evCvtX, cudaEventDisableTiming);
        cudaEventCreateWithFlags(&evDual, cudaEventDisableTiming);
        cudaEventCreateWithFlags(&evW,    cudaEventDisableTiming);
        cudaEventCreateWithFlags(&evSA,   cudaEventDisableTiming);
        for (int b = 0; b < B_; b++)
            cudaEventCreateWithFlags(&evSM[b], cudaEventDisableTiming);
        cudaFuncSetAttribute(k_weights_mma, cudaFuncAttributeMaxDynamicSharedMemorySize, SMW_BYTES);
        cudaFuncSetAttribute(k_score_mma,   cudaFuncAttributeMaxDynamicSharedMemorySize, SMSC_BYTES);
        cudaFuncSetAttribute(k_sa_mma,      cudaFuncAttributeMaxDynamicSharedMemorySize, SMS_BYTES);
        cudaFuncSetAttribute(k_dual_mma,    cudaFuncAttributeMaxDynamicSharedMemorySize, SMD_BYTES);
    }

    // ---- fork s2: chain A = cvt_wp -> weights -> dual -> bias ----
    cudaEventRecord(evFork, 0);
    cudaStreamWaitEvent(s2, evFork, 0);
    k_cvt_wp<<<(1024*4096)/(256*4), 256, 0, s2>>>(wp);

    // main: prologue
    k_supports<<<dim3(N_/16, N_/16), dim3(16,16)>>>(e1, e2);
    cudaEventRecord(evSup, 0);
    cudaStreamWaitEvent(s2, evSup, 0);
    k_softmaxA<<<N_, 256>>>(A_sym);
    k_cvt_x   <<<dim3(N_/64, BT_), 256>>>(x);
    cudaEventRecord(evCvtX, 0);

    // s2: weights (needs supports), then dual (needs softmaxA+cvt_x), then bias
    k_weights_mma<<<dim3(32, 8), 256, SMW_BYTES, s2>>>();
    cudaStreamWaitEvent(s2, evCvtX, 0);
    k_dual_mma<<<dim3(8, BT_/2), 256, SMD_BYTES, s2>>>(gamma, out);
    cudaEventRecord(evDual, s2);
    k_bias_part<<<dim3(N_/64, 8), 256, 0, s2>>>(bp);
    k_bias_red <<<(N_*C_)/256, 256, 0, s2>>>();
    cudaEventRecord(evW, s2);

    // s3: sa pipeline — must wait for dual's '=' writes to out
    cudaStreamWaitEvent(s3, evDual, 0);

    // main: per-b score + softmax, s3 trails with sa(b)
    for (int b = 0; b < B_; b++) {
        k_score_mma<<<dim3(8, 8, T_), 256, SMSC_BYTES>>>(b * T_);
        k_softmax_t<<<(N_*N_)/(256*4), 256>>>(b);
        cudaEventRecord(evSM[b], 0);
        cudaStreamWaitEvent(s3, evSM[b], 0);
        k_sa_mma<<<dim3(8, T_), 256, SMS_BYTES, s3>>>(b, beta, out);
    }
    cudaEventRecord(evSA, s3);

    // ---- join: gconv needs weights+bias (s2), xg (dual), and all sa done ----
    cudaStreamWaitEvent(0, evSA, 0);
    cudaStreamWaitEvent(0, evW, 0);
    k_gconv<<<N_, 256>>>(alpha, out);
}